// round 1
// baseline (speedup 1.0000x reference)
#include <cuda_runtime.h>
#include <math.h>
#include <stdint.h>

#define N_NODES 100000
#define N_EDGES 1600000
#define IN_F    16
#define HID     100
#define OUTF    3

// Scratch buffers (allocations are forbidden; device globals are the sanctioned path)
__device__ __align__(16) float g_h  [N_NODES * HID];
__device__ __align__(16) float g_h2 [N_NODES * HID];
__device__ __align__(16) float g_red[N_NODES * HID];

// ---------------------------------------------------------------------------
// Generic tiled GEMM + activation.
//   out[n, 0:100] = act( in[n, 0:KDIM] @ W[KDIM x 100] + b )
// CONCAT: in row = concat(in1[n,0:100], in2[n,0:100]); else in1 row stride KDIM.
// Block: 512 threads. Node tile: 128. Thread: 2 nodes x 16 output cols.
// smem: sW[KDIM][128] (cols padded to 128, zero-filled >=100)
//       sIn[128][KDIM+4] (stride padded to dodge bank conflicts)
// ACT: 0 = tanh, 1 = relu
// ---------------------------------------------------------------------------
template <int KDIM, int ACT, bool CONCAT>
__global__ __launch_bounds__(512, 1)
void gemm_act_kernel(const float* __restrict__ in1,
                     const float* __restrict__ in2,
                     const float* __restrict__ W,
                     const float* __restrict__ b,
                     float* __restrict__ out,
                     int n_nodes)
{
    extern __shared__ float sm[];
    float* sW  = sm;                     // KDIM * 128
    float* sIn = sm + KDIM * 128;        // 128 * (KDIM + 4)
    const int SIN_STRIDE = KDIM + 4;

    const int tid   = threadIdx.x;
    const int node0 = blockIdx.x * 128;

    // Load weights: W is [KDIM][100] row-major -> pad cols to 128 with zeros
    for (int i = tid; i < KDIM * 128; i += 512) {
        int k = i >> 7;
        int c = i & 127;
        sW[i] = (c < HID) ? W[k * HID + c] : 0.0f;
    }

    // Load input tile
    for (int i = tid; i < 128 * KDIM; i += 512) {
        int nl = i / KDIM;
        int k  = i - nl * KDIM;
        int n  = node0 + nl;
        float v = 0.0f;
        if (n < n_nodes) {
            if (CONCAT) {
                v = (k < HID) ? in1[n * HID + k] : in2[n * HID + (k - HID)];
            } else {
                v = in1[n * KDIM + k];
            }
        }
        sIn[nl * SIN_STRIDE + k] = v;
    }
    __syncthreads();

    const int og = tid & 7;    // output col group: cols [og*16, og*16+16)
    const int ng = tid >> 3;   // node pair: nodes ng*2, ng*2+1

    float acc0[16], acc1[16];
#pragma unroll
    for (int j = 0; j < 16; ++j) { acc0[j] = 0.0f; acc1[j] = 0.0f; }

    const float* sin0 = sIn + (ng * 2)     * SIN_STRIDE;
    const float* sin1 = sIn + (ng * 2 + 1) * SIN_STRIDE;
    const float* wbase = sW + (og << 4);

#pragma unroll 4
    for (int k = 0; k < KDIM; ++k) {
        float a0 = sin0[k];
        float a1 = sin1[k];
        const float4* wv = reinterpret_cast<const float4*>(wbase + (k << 7));
        float4 w0 = wv[0], w1 = wv[1], w2 = wv[2], w3 = wv[3];
        float wr[16] = { w0.x, w0.y, w0.z, w0.w,
                         w1.x, w1.y, w1.z, w1.w,
                         w2.x, w2.y, w2.z, w2.w,
                         w3.x, w3.y, w3.z, w3.w };
#pragma unroll
        for (int j = 0; j < 16; ++j) {
            acc0[j] += a0 * wr[j];
            acc1[j] += a1 * wr[j];
        }
    }

    const int n0   = node0 + ng * 2;
    const int col0 = og << 4;
#pragma unroll
    for (int j = 0; j < 16; ++j) {
        int c = col0 + j;
        if (c < HID) {
            float bias = b[c];
            float r0 = acc0[j] + bias;
            float r1 = acc1[j] + bias;
            if (ACT == 0) { r0 = tanhf(r0); r1 = tanhf(r1); }
            else          { r0 = fmaxf(r0, 0.0f); r1 = fmaxf(r1, 0.0f); }
            if (n0     < n_nodes) out[n0       * HID + c] = r0;
            if (n0 + 1 < n_nodes) out[(n0 + 1) * HID + c] = r1;
        }
    }
}

// ---------------------------------------------------------------------------
// Edge scatter: reduced[dst] += edge_w * h[src]   (segment_sum)
// One thread per (edge, 4-float chunk): 25 chunks of float4 per edge.
// Vector reduction red.global.add.v4.f32 (sm_90+) -> 4x fewer L2 atomic ops.
// Row stride is 400B so every chunk is 16B aligned.
// ---------------------------------------------------------------------------
__global__ __launch_bounds__(256)
void scatter_kernel(const float* __restrict__ h,
                    const float* __restrict__ ef,
                    const int*   __restrict__ src,
                    const int*   __restrict__ dst,
                    float* __restrict__ red)
{
    unsigned idx = blockIdx.x * 256u + threadIdx.x;   // < E*25 = 40,000,000
    if (idx >= (unsigned)N_EDGES * 25u) return;
    unsigned e = idx / 25u;
    unsigned c = idx - e * 25u;

    float w = ef[e];
    int   s = src[e];
    int   d = dst[e];

    const float4 v = *reinterpret_cast<const float4*>(h + (size_t)s * HID + c * 4u);
    float* p = red + (size_t)d * HID + c * 4u;
    asm volatile("red.global.add.v4.f32 [%0], {%1, %2, %3, %4};"
                 :: "l"(p), "f"(v.x * w), "f"(v.y * w), "f"(v.z * w), "f"(v.w * w)
                 : "memory");
}

// ---------------------------------------------------------------------------
// Output head: y[n] = sigmoid(h[n,0:100] @ W_out[100x3] + b_out)
// ---------------------------------------------------------------------------
__global__ __launch_bounds__(256)
void out_kernel(const float* __restrict__ h,
                const float* __restrict__ Wo,
                const float* __restrict__ bo,
                float* __restrict__ y,
                int n_nodes)
{
    __shared__ float sW[HID * OUTF];
    int tid = threadIdx.x;
    for (int i = tid; i < HID * OUTF; i += 256) sW[i] = Wo[i];
    __syncthreads();

    int node = blockIdx.x * 256 + tid;
    if (node >= n_nodes) return;

    float a0 = bo[0], a1 = bo[1], a2 = bo[2];
    const float4* hv = reinterpret_cast<const float4*>(h + (size_t)node * HID);
#pragma unroll
    for (int kb = 0; kb < 25; ++kb) {
        float4 v = hv[kb];
        int k = kb * 4;
        a0 += v.x * sW[(k+0)*3+0]; a1 += v.x * sW[(k+0)*3+1]; a2 += v.x * sW[(k+0)*3+2];
        a0 += v.y * sW[(k+1)*3+0]; a1 += v.y * sW[(k+1)*3+1]; a2 += v.y * sW[(k+1)*3+2];
        a0 += v.z * sW[(k+2)*3+0]; a1 += v.z * sW[(k+2)*3+1]; a2 += v.z * sW[(k+2)*3+2];
        a0 += v.w * sW[(k+3)*3+0]; a1 += v.w * sW[(k+3)*3+1]; a2 += v.w * sW[(k+3)*3+2];
    }
    y[(size_t)node * 3 + 0] = 1.0f / (1.0f + expf(-a0));
    y[(size_t)node * 3 + 1] = 1.0f / (1.0f + expf(-a1));
    y[(size_t)node * 3 + 2] = 1.0f / (1.0f + expf(-a2));
}

// ---------------------------------------------------------------------------
extern "C" void kernel_launch(void* const* d_in, const int* in_sizes, int n_in,
                              void* d_out, int out_size)
{
    const float* x      = (const float*)d_in[0];
    const float* ef     = (const float*)d_in[1];
    const int*   src    = (const int*)  d_in[2];
    const int*   dst    = (const int*)  d_in[3];
    const float* W_lift = (const float*)d_in[4];
    const float* b_lift = (const float*)d_in[5];
    const float* W1     = (const float*)d_in[6];
    const float* b1     = (const float*)d_in[7];
    const float* W2     = (const float*)d_in[8];
    const float* b2     = (const float*)d_in[9];
    const float* W3     = (const float*)d_in[10];
    const float* b3     = (const float*)d_in[11];
    const float* W_out  = (const float*)d_in[12];
    const float* b_out  = (const float*)d_in[13];
    float* y = (float*)d_out;

    float *h, *h2, *red;
    cudaGetSymbolAddress((void**)&h,   g_h);
    cudaGetSymbolAddress((void**)&h2,  g_h2);
    cudaGetSymbolAddress((void**)&red, g_red);

    const int GEMM_GRID = (N_NODES + 127) / 128;               // 782
    const size_t SMEM_LIFT = (IN_F * 128 + 128 * (IN_F + 4)) * sizeof(float);   // 18432
    const size_t SMEM_MPL  = (200  * 128 + 128 * (200  + 4)) * sizeof(float);   // 206848

    cudaFuncSetAttribute((const void*)gemm_act_kernel<200, 1, true>,
                         cudaFuncAttributeMaxDynamicSharedMemorySize, (int)SMEM_MPL);

    // 1) lift: h = tanh(x @ W_lift + b_lift)
    gemm_act_kernel<IN_F, 0, false><<<GEMM_GRID, 512, SMEM_LIFT>>>(
        x, nullptr, W_lift, b_lift, h, N_NODES);

    const unsigned SCAT_GRID = ((unsigned)N_EDGES * 25u + 255u) / 256u;  // 156250
    const size_t RED_BYTES = (size_t)N_NODES * HID * sizeof(float);

    const float* Ws[3] = { W1, W2, W3 };
    const float* bs[3] = { b1, b2, b3 };
    float* bufs[4] = { h, h2, h, h2 };   // ping-pong

    for (int l = 0; l < 3; ++l) {
        float* hin  = bufs[l];
        float* hout = bufs[l + 1];
        cudaMemsetAsync(red, 0, RED_BYTES);
        scatter_kernel<<<SCAT_GRID, 256>>>(hin, ef, src, dst, red);
        gemm_act_kernel<200, 1, true><<<GEMM_GRID, 512, SMEM_MPL>>>(
            hin, red, Ws[l], bs[l], hout, N_NODES);
    }

    // 3) output head from final buffer (h2 after layer 3)
    out_kernel<<<(N_NODES + 255) / 256, 256>>>(h2, W_out, b_out, y, N_NODES);

    (void)in_sizes; (void)n_in; (void)out_size;
}

// round 2
// speedup vs baseline: 2.3774x; 2.3774x over previous
#include <cuda_runtime.h>
#include <math.h>
#include <stdint.h>

#define N_NODES 100000
#define N_EDGES 1600000
#define IN_F    16
#define HID     100
#define OUTF    3

// Scratch buffers (allocations are forbidden; device globals are the sanctioned path)
__device__ __align__(16) float g_h  [N_NODES * HID];
__device__ __align__(16) float g_h2 [N_NODES * HID];
__device__ __align__(16) float g_red[N_NODES * HID];

// ---------------------------------------------------------------------------
// Tiled GEMM + activation, conflict-free shared access.
//   out[n, 0:100] = act( in[n, 0:KDIM] @ W[KDIM x 100] + b )
// Block: 512 threads (16 warps). M-tile = 128 nodes. N padded to 128 cols.
// Thread micro-tile: 8 nodes x 4 cols.
//   warp wp (0..15) -> nodes wp*8 .. wp*8+7
//   lane (0..31)    -> cols  lane*4 .. lane*4+3
// smem:
//   sW [KDIM][128]        weight LDS.128 at lane*16B: 512B linear, conflict-free
//   sIn[128][KDIM+4]      activation LDS.128: all lanes same addr -> broadcast
// ACT: 0 = tanh, 1 = relu
// ---------------------------------------------------------------------------
template <int KDIM, int ACT, bool CONCAT>
__global__ __launch_bounds__(512, 1)
void gemm_act_kernel(const float* __restrict__ in1,
                     const float* __restrict__ in2,
                     const float* __restrict__ W,
                     const float* __restrict__ b,
                     float* __restrict__ out,
                     int n_nodes)
{
    extern __shared__ float sm[];
    constexpr int SSTR = KDIM + 4;          // float stride; (KDIM+4)*4 bytes is 16B-multiple
    float* sW  = sm;                        // KDIM * 128
    float* sIn = sm + KDIM * 128;           // 128 * SSTR

    const int tid   = threadIdx.x;
    const int node0 = blockIdx.x * 128;

    // Load weights: W is [KDIM][100] row-major -> pad cols to 128 with zeros
    for (int i = tid; i < KDIM * 128; i += 512) {
        int k = i >> 7;
        int c = i & 127;
        sW[i] = (c < HID) ? W[k * HID + c] : 0.0f;
    }

    // Load input tile row-major [node][k] (coalesced along k)
    for (int i = tid; i < 128 * KDIM; i += 512) {
        int nl = i / KDIM;
        int k  = i - nl * KDIM;
        int n  = node0 + nl;
        float v = 0.0f;
        if (n < n_nodes) {
            if (CONCAT) v = (k < HID) ? in1[n * HID + k] : in2[n * HID + (k - HID)];
            else        v = in1[n * KDIM + k];
        }
        sIn[nl * SSTR + k] = v;
    }
    __syncthreads();

    const int lane = tid & 31;
    const int wp   = tid >> 5;
    const float* abase = sIn + wp * 8 * SSTR;
    const float* wbase = sW + lane * 4;

    float4 acc[8];
#pragma unroll
    for (int j = 0; j < 8; ++j) acc[j] = make_float4(0.f, 0.f, 0.f, 0.f);

#pragma unroll 2
    for (int k0 = 0; k0 < KDIM; k0 += 4) {
        const float4 w0 = *reinterpret_cast<const float4*>(wbase + (k0 + 0) * 128);
        const float4 w1 = *reinterpret_cast<const float4*>(wbase + (k0 + 1) * 128);
        const float4 w2 = *reinterpret_cast<const float4*>(wbase + (k0 + 2) * 128);
        const float4 w3 = *reinterpret_cast<const float4*>(wbase + (k0 + 3) * 128);
#pragma unroll
        for (int j = 0; j < 8; ++j) {
            const float4 a = *reinterpret_cast<const float4*>(abase + j * SSTR + k0);
            acc[j].x += a.x * w0.x; acc[j].y += a.x * w0.y; acc[j].z += a.x * w0.z; acc[j].w += a.x * w0.w;
            acc[j].x += a.y * w1.x; acc[j].y += a.y * w1.y; acc[j].z += a.y * w1.z; acc[j].w += a.y * w1.w;
            acc[j].x += a.z * w2.x; acc[j].y += a.z * w2.y; acc[j].z += a.z * w2.z; acc[j].w += a.z * w2.w;
            acc[j].x += a.w * w3.x; acc[j].y += a.w * w3.y; acc[j].z += a.w * w3.z; acc[j].w += a.w * w3.w;
        }
    }

    // Store: only lanes 0..24 hold real columns (cols < 100); float4 aligned (n*400 + lane*16)
    if (lane < 25) {
        const float4 bias = *reinterpret_cast<const float4*>(b + lane * 4);
#pragma unroll
        for (int j = 0; j < 8; ++j) {
            int n = node0 + wp * 8 + j;
            if (n < n_nodes) {
                float4 r;
                r.x = acc[j].x + bias.x; r.y = acc[j].y + bias.y;
                r.z = acc[j].z + bias.z; r.w = acc[j].w + bias.w;
                if (ACT == 0) { r.x = tanhf(r.x); r.y = tanhf(r.y); r.z = tanhf(r.z); r.w = tanhf(r.w); }
                else { r.x = fmaxf(r.x, 0.f); r.y = fmaxf(r.y, 0.f); r.z = fmaxf(r.z, 0.f); r.w = fmaxf(r.w, 0.f); }
                *reinterpret_cast<float4*>(out + (size_t)n * HID + lane * 4) = r;
            }
        }
    }
}

// ---------------------------------------------------------------------------
// Edge scatter: reduced[dst] += edge_w * h[src]   (segment_sum)
// One thread per (edge, 4-float chunk): 25 float4 chunks per edge.
// Chunk-parallel layout keeps the 400B row gather coalesced across the warp;
// scalar (ef/src/dst) replays dedup in L1.
// ---------------------------------------------------------------------------
__global__ __launch_bounds__(256)
void scatter_kernel(const float* __restrict__ h,
                    const float* __restrict__ ef,
                    const int*   __restrict__ src,
                    const int*   __restrict__ dst,
                    float* __restrict__ red)
{
    unsigned idx = blockIdx.x * 256u + threadIdx.x;   // < E*25 = 40,000,000
    if (idx >= (unsigned)N_EDGES * 25u) return;
    unsigned e = idx / 25u;
    unsigned c = idx - e * 25u;

    float w = ef[e];
    int   s = src[e];
    int   d = dst[e];

    const float4 v = *reinterpret_cast<const float4*>(h + (size_t)s * HID + c * 4u);
    float* p = red + (size_t)d * HID + c * 4u;
    asm volatile("red.global.add.v4.f32 [%0], {%1, %2, %3, %4};"
                 :: "l"(p), "f"(v.x * w), "f"(v.y * w), "f"(v.z * w), "f"(v.w * w)
                 : "memory");
}

// ---------------------------------------------------------------------------
// Output head: y[n] = sigmoid(h[n,0:100] @ W_out[100x3] + b_out)
// ---------------------------------------------------------------------------
__global__ __launch_bounds__(256)
void out_kernel(const float* __restrict__ h,
                const float* __restrict__ Wo,
                const float* __restrict__ bo,
                float* __restrict__ y,
                int n_nodes)
{
    __shared__ float sW[HID * OUTF];
    int tid = threadIdx.x;
    for (int i = tid; i < HID * OUTF; i += 256) sW[i] = Wo[i];
    __syncthreads();

    int node = blockIdx.x * 256 + tid;
    if (node >= n_nodes) return;

    float a0 = bo[0], a1 = bo[1], a2 = bo[2];
    const float4* hv = reinterpret_cast<const float4*>(h + (size_t)node * HID);
#pragma unroll
    for (int kb = 0; kb < 25; ++kb) {
        float4 v = hv[kb];
        int k = kb * 4;
        a0 += v.x * sW[(k+0)*3+0]; a1 += v.x * sW[(k+0)*3+1]; a2 += v.x * sW[(k+0)*3+2];
        a0 += v.y * sW[(k+1)*3+0]; a1 += v.y * sW[(k+1)*3+1]; a2 += v.y * sW[(k+1)*3+2];
        a0 += v.z * sW[(k+2)*3+0]; a1 += v.z * sW[(k+2)*3+1]; a2 += v.z * sW[(k+2)*3+2];
        a0 += v.w * sW[(k+3)*3+0]; a1 += v.w * sW[(k+3)*3+1]; a2 += v.w * sW[(k+3)*3+2];
    }
    y[(size_t)node * 3 + 0] = 1.0f / (1.0f + expf(-a0));
    y[(size_t)node * 3 + 1] = 1.0f / (1.0f + expf(-a1));
    y[(size_t)node * 3 + 2] = 1.0f / (1.0f + expf(-a2));
}

// ---------------------------------------------------------------------------
extern "C" void kernel_launch(void* const* d_in, const int* in_sizes, int n_in,
                              void* d_out, int out_size)
{
    const float* x      = (const float*)d_in[0];
    const float* ef     = (const float*)d_in[1];
    const int*   src    = (const int*)  d_in[2];
    const int*   dst    = (const int*)  d_in[3];
    const float* W_lift = (const float*)d_in[4];
    const float* b_lift = (const float*)d_in[5];
    const float* W1     = (const float*)d_in[6];
    const float* b1     = (const float*)d_in[7];
    const float* W2     = (const float*)d_in[8];
    const float* b2     = (const float*)d_in[9];
    const float* W3     = (const float*)d_in[10];
    const float* b3     = (const float*)d_in[11];
    const float* W_out  = (const float*)d_in[12];
    const float* b_out  = (const float*)d_in[13];
    float* y = (float*)d_out;

    float *h, *h2, *red;
    cudaGetSymbolAddress((void**)&h,   g_h);
    cudaGetSymbolAddress((void**)&h2,  g_h2);
    cudaGetSymbolAddress((void**)&red, g_red);

    const int GEMM_GRID = (N_NODES + 127) / 128;               // 782
    const size_t SMEM_LIFT = (IN_F * 128 + 128 * (IN_F + 4)) * sizeof(float);   // 18432
    const size_t SMEM_MPL  = (200  * 128 + 128 * (200  + 4)) * sizeof(float);   // 206848

    cudaFuncSetAttribute((const void*)gemm_act_kernel<200, 1, true>,
                         cudaFuncAttributeMaxDynamicSharedMemorySize, (int)SMEM_MPL);

    // 1) lift: h = tanh(x @ W_lift + b_lift)
    gemm_act_kernel<IN_F, 0, false><<<GEMM_GRID, 512, SMEM_LIFT>>>(
        x, nullptr, W_lift, b_lift, h, N_NODES);

    const unsigned SCAT_GRID = ((unsigned)N_EDGES * 25u + 255u) / 256u;  // 156250
    const size_t RED_BYTES = (size_t)N_NODES * HID * sizeof(float);

    const float* Ws[3] = { W1, W2, W3 };
    const float* bs[3] = { b1, b2, b3 };
    float* bufs[4] = { h, h2, h, h2 };   // ping-pong

    for (int l = 0; l < 3; ++l) {
        float* hin  = bufs[l];
        float* hout = bufs[l + 1];
        cudaMemsetAsync(red, 0, RED_BYTES);
        scatter_kernel<<<SCAT_GRID, 256>>>(hin, ef, src, dst, red);
        gemm_act_kernel<200, 1, true><<<GEMM_GRID, 512, SMEM_MPL>>>(
            hin, red, Ws[l], bs[l], hout, N_NODES);
    }

    // 3) output head from final buffer (h2 after layer 3)
    out_kernel<<<(N_NODES + 255) / 256, 256>>>(h2, W_out, b_out, y, N_NODES);

    (void)in_sizes; (void)n_in; (void)out_size;
}

// round 4
// speedup vs baseline: 2.4581x; 1.0340x over previous
#include <cuda_runtime.h>
#include <cuda_bf16.h>
#include <math.h>
#include <stdint.h>

#define N_NODES 100000
#define N_EDGES 1600000
#define IN_F    16
#define HID     100
#define OUTF    3

// K' layout: 3 sections of 208 (200 real + 8 pad), total 624 = 39 x 16
#define SEC   208
#define KP    624
#define KC    48          // K-chunk (3 mma-k16 per chunk), 13 chunks
#define NCH   (KP / KC)

// ---------------------------------------------------------------------------
// Scratch (device globals; allocation APIs are forbidden)
// ---------------------------------------------------------------------------
__device__ __align__(16) float g_h  [N_NODES * HID];
__device__ __align__(16) float g_h2 [N_NODES * HID];
__device__ __align__(16) float g_red[N_NODES * HID];
// Pre-built bf16 B' images: [layer(3)][kp(624)][col(128)]
__device__ __align__(16) __nv_bfloat16 g_Bmma[3 * KP * 128];

__device__ __forceinline__ uint32_t smem_u32(const void* p) {
    uint32_t a;
    asm("{ .reg .u64 t; cvta.to.shared.u64 t, %1; cvt.u32.u64 %0, t; }" : "=r"(a) : "l"(p));
    return a;
}

// ---------------------------------------------------------------------------
// Prep: B'[l][kp][col] where B = W^T (col = out-col, kk = in-dim)
// sections: 0 -> bf16_hi(W), 1 -> bf16_hi(W), 2 -> bf16_lo(W)
// ---------------------------------------------------------------------------
__global__ __launch_bounds__(256)
void prep_B_kernel(const float* __restrict__ W1, const float* __restrict__ W2,
                   const float* __restrict__ W3)
{
    int i = blockIdx.x * 256 + threadIdx.x;
    if (i >= 3 * KP * 128) return;
    int l   = i / (KP * 128);
    int r   = i - l * (KP * 128);
    int kp  = r >> 7;
    int col = r & 127;
    int sec = (kp >= 2 * SEC) ? 2 : (kp >= SEC ? 1 : 0);
    int kk  = kp - sec * SEC;

    const float* W = (l == 0) ? W1 : (l == 1) ? W2 : W3;
    float w = (kk < 2 * HID && col < HID) ? W[kk * HID + col] : 0.0f;

    __nv_bfloat16 hi = __float2bfloat16(w);
    __nv_bfloat16 o  = (sec == 2) ? __float2bfloat16(w - __bfloat162float(hi)) : hi;
    g_Bmma[i] = o;
}

// ---------------------------------------------------------------------------
// MPL GEMM via mma.sync m16n8k16 bf16 (hi/lo split folded into K'=624):
//   out[n, 0:100] = relu( concat(h[n], red[n]) @ W + b )
// CTA: 128 nodes x 128 cols, 512 thr = 16 warps (8 along M x 2 along N).
// Warp tile: 16 x 64.  Per-thread acc: 8 frags x 4 f32.
// smem padded (+8 bf16) so ldmatrix row pointers are bank-conflict-free.
// ---------------------------------------------------------------------------
__global__ __launch_bounds__(512, 2)
void mpl_gemm_mma(const float* __restrict__ h,
                  const float* __restrict__ red,
                  const __nv_bfloat16* __restrict__ Bg,  // layer base in g_Bmma
                  const float* __restrict__ b,
                  float* __restrict__ out,
                  int n_nodes)
{
    __shared__ __align__(16) __nv_bfloat16 sA[128 * 56];   // stride 56 (112B)
    __shared__ __align__(16) __nv_bfloat16 sB[KC * 136];   // stride 136 (272B)

    const int tid    = threadIdx.x;
    const int wid    = tid >> 5;
    const int lane   = tid & 31;
    const int warp_m = wid & 7;
    const int warp_n = wid >> 3;
    const int node0  = blockIdx.x * 128;

    float acc[8][4];
#pragma unroll
    for (int f = 0; f < 8; ++f)
#pragma unroll
        for (int j = 0; j < 4; ++j) acc[f][j] = 0.0f;

    // ldmatrix lane addressing (canonical m16n8k16 pattern)
    const int lrow  = lane & 15;
    const int lkoff = (lane >> 4) << 3;
    const uint32_t aBase = smem_u32(sA) + (uint32_t)(((warp_m * 16 + lrow) * 56 + lkoff) * 2);
    const uint32_t bBase = smem_u32(sB) + (uint32_t)((lrow * 136 + warp_n * 64 + lkoff) * 2);

    for (int ch = 0; ch < NCH; ++ch) {
        __syncthreads();   // protect smem from previous chunk's readers

        // ---- fill A chunk: fp32 -> bf16 (hi or lo per section) ----
        const int kpb = ch * KC;
        for (int i = tid; i < 128 * KC; i += 512) {
            int row = i / KC;
            int kl  = i - row * KC;
            int kp  = kpb + kl;
            int sec = (kp >= 2 * SEC) ? 2 : (kp >= SEC ? 1 : 0);
            int kk  = kp - sec * SEC;
            int n   = node0 + row;
            float v = 0.0f;
            if (n < n_nodes) {
                if (kk < HID)          v = h[n * HID + kk];
                else if (kk < 2 * HID) v = red[n * HID + kk - HID];
            }
            __nv_bfloat16 hi = __float2bfloat16(v);
            sA[row * 56 + kl] = (sec == 1)
                ? __float2bfloat16(v - __bfloat162float(hi)) : hi;
        }
        // ---- fill B chunk: coalesced copy of prebuilt image (uint2 = 4 bf16) ----
        {
            const uint2* src = reinterpret_cast<const uint2*>(Bg + (size_t)kpb * 128);
            for (int i = tid; i < KC * 32; i += 512) {
                int rowk = i >> 5;
                int c4   = (i & 31) << 2;
                uint2 v = src[i];
                *reinterpret_cast<uint2*>(&sB[rowk * 136 + c4]) = v;
            }
        }
        __syncthreads();

        // ---- compute: 3 k16 steps per chunk ----
#pragma unroll
        for (int kf = 0; kf < KC / 16; ++kf) {
            uint32_t a0, a1, a2, a3;
            asm volatile("ldmatrix.sync.aligned.m8n8.x4.shared.b16 {%0,%1,%2,%3}, [%4];"
                         : "=r"(a0), "=r"(a1), "=r"(a2), "=r"(a3)
                         : "r"(aBase + (uint32_t)(kf * 16 * 2)));
#pragma unroll
            for (int nb = 0; nb < 4; ++nb) {
                uint32_t b0, b1, b2, b3;
                asm volatile("ldmatrix.sync.aligned.m8n8.x4.trans.shared.b16 {%0,%1,%2,%3}, [%4];"
                             : "=r"(b0), "=r"(b1), "=r"(b2), "=r"(b3)
                             : "r"(bBase + (uint32_t)((kf * 16 * 136 + nb * 16) * 2)));
                asm volatile("mma.sync.aligned.m16n8k16.row.col.f32.bf16.bf16.f32 "
                             "{%0,%1,%2,%3}, {%4,%5,%6,%7}, {%8,%9}, {%0,%1,%2,%3};"
                             : "+f"(acc[nb * 2][0]), "+f"(acc[nb * 2][1]),
                               "+f"(acc[nb * 2][2]), "+f"(acc[nb * 2][3])
                             : "r"(a0), "r"(a1), "r"(a2), "r"(a3), "r"(b0), "r"(b1));
                asm volatile("mma.sync.aligned.m16n8k16.row.col.f32.bf16.bf16.f32 "
                             "{%0,%1,%2,%3}, {%4,%5,%6,%7}, {%8,%9}, {%0,%1,%2,%3};"
                             : "+f"(acc[nb * 2 + 1][0]), "+f"(acc[nb * 2 + 1][1]),
                               "+f"(acc[nb * 2 + 1][2]), "+f"(acc[nb * 2 + 1][3])
                             : "r"(a0), "r"(a1), "r"(a2), "r"(a3), "r"(b2), "r"(b3));
            }
        }
    }

    // ---- epilogue: bias + relu + float2 stores ----
    const int gr = lane >> 2;
    const int tc = lane & 3;
    const int r0 = node0 + warp_m * 16 + gr;
    const int r1 = r0 + 8;
#pragma unroll
    for (int f = 0; f < 8; ++f) {
        int col = warp_n * 64 + f * 8 + tc * 2;
        if (col < HID) {
            float b0 = b[col], b1 = b[col + 1];
            if (r0 < n_nodes) {
                float2 v;
                v.x = fmaxf(acc[f][0] + b0, 0.f);
                v.y = fmaxf(acc[f][1] + b1, 0.f);
                *reinterpret_cast<float2*>(out + (size_t)r0 * HID + col) = v;
            }
            if (r1 < n_nodes) {
                float2 v;
                v.x = fmaxf(acc[f][2] + b0, 0.f);
                v.y = fmaxf(acc[f][3] + b1, 0.f);
                *reinterpret_cast<float2*>(out + (size_t)r1 * HID + col) = v;
            }
        }
    }
}

// ---------------------------------------------------------------------------
// Lift GEMM (FFMA; tiny K=16): h = tanh(x @ W_lift + b_lift)
// ---------------------------------------------------------------------------
template <int KDIM>
__global__ __launch_bounds__(512, 1)
void lift_gemm_kernel(const float* __restrict__ in1,
                      const float* __restrict__ W,
                      const float* __restrict__ b,
                      float* __restrict__ out,
                      int n_nodes)
{
    extern __shared__ float sm[];
    constexpr int SSTR = KDIM + 4;
    float* sW  = sm;                 // KDIM * 128
    float* sIn = sm + KDIM * 128;    // 128 * SSTR

    const int tid   = threadIdx.x;
    const int node0 = blockIdx.x * 128;

    for (int i = tid; i < KDIM * 128; i += 512) {
        int k = i >> 7, c = i & 127;
        sW[i] = (c < HID) ? W[k * HID + c] : 0.0f;
    }
    for (int i = tid; i < 128 * KDIM; i += 512) {
        int nl = i / KDIM, k = i - nl * KDIM;
        int n  = node0 + nl;
        sIn[nl * SSTR + k] = (n < n_nodes) ? in1[n * KDIM + k] : 0.0f;
    }
    __syncthreads();

    const int lane = tid & 31;
    const int wp   = tid >> 5;
    const float* abase = sIn + wp * 8 * SSTR;
    const float* wbase = sW + lane * 4;

    float4 acc[8];
#pragma unroll
    for (int j = 0; j < 8; ++j) acc[j] = make_float4(0.f, 0.f, 0.f, 0.f);

#pragma unroll
    for (int k0 = 0; k0 < KDIM; k0 += 4) {
        const float4 w0 = *reinterpret_cast<const float4*>(wbase + (k0 + 0) * 128);
        const float4 w1 = *reinterpret_cast<const float4*>(wbase + (k0 + 1) * 128);
        const float4 w2 = *reinterpret_cast<const float4*>(wbase + (k0 + 2) * 128);
        const float4 w3 = *reinterpret_cast<const float4*>(wbase + (k0 + 3) * 128);
#pragma unroll
        for (int j = 0; j < 8; ++j) {
            const float4 a = *reinterpret_cast<const float4*>(abase + j * SSTR + k0);
            acc[j].x += a.x * w0.x; acc[j].y += a.x * w0.y; acc[j].z += a.x * w0.z; acc[j].w += a.x * w0.w;
            acc[j].x += a.y * w1.x; acc[j].y += a.y * w1.y; acc[j].z += a.y * w1.z; acc[j].w += a.y * w1.w;
            acc[j].x += a.z * w2.x; acc[j].y += a.z * w2.y; acc[j].z += a.z * w2.z; acc[j].w += a.z * w2.w;
            acc[j].x += a.w * w3.x; acc[j].y += a.w * w3.y; acc[j].z += a.w * w3.z; acc[j].w += a.w * w3.w;
        }
    }

    if (lane < 25) {
        const float4 bias = *reinterpret_cast<const float4*>(b + lane * 4);
#pragma unroll
        for (int j = 0; j < 8; ++j) {
            int n = node0 + wp * 8 + j;
            if (n < n_nodes) {
                float4 r;
                r.x = tanhf(acc[j].x + bias.x); r.y = tanhf(acc[j].y + bias.y);
                r.z = tanhf(acc[j].z + bias.z); r.w = tanhf(acc[j].w + bias.w);
                *reinterpret_cast<float4*>(out + (size_t)n * HID + lane * 4) = r;
            }
        }
    }
}

// ---------------------------------------------------------------------------
// Edge scatter: reduced[dst] += edge_w * h[src]
// ---------------------------------------------------------------------------
__global__ __launch_bounds__(256)
void scatter_kernel(const float* __restrict__ h,
                    const float* __restrict__ ef,
                    const int*   __restrict__ src,
                    const int*   __restrict__ dst,
                    float* __restrict__ red)
{
    unsigned idx = blockIdx.x * 256u + threadIdx.x;   // < E*25 = 40,000,000
    if (idx >= (unsigned)N_EDGES * 25u) return;
    unsigned e = idx / 25u;
    unsigned c = idx - e * 25u;

    float w = ef[e];
    int   s = src[e];
    int   d = dst[e];

    const float4 v = *reinterpret_cast<const float4*>(h + (size_t)s * HID + c * 4u);
    float* p = red + (size_t)d * HID + c * 4u;
    asm volatile("red.global.add.v4.f32 [%0], {%1, %2, %3, %4};"
                 :: "l"(p), "f"(v.x * w), "f"(v.y * w), "f"(v.z * w), "f"(v.w * w)
                 : "memory");
}

// ---------------------------------------------------------------------------
// Output head: y[n] = sigmoid(h[n,0:100] @ W_out[100x3] + b_out)
// ---------------------------------------------------------------------------
__global__ __launch_bounds__(256)
void out_kernel(const float* __restrict__ h,
                const float* __restrict__ Wo,
                const float* __restrict__ bo,
                float* __restrict__ y,
                int n_nodes)
{
    __shared__ float sW[HID * OUTF];
    int tid = threadIdx.x;
    for (int i = tid; i < HID * OUTF; i += 256) sW[i] = Wo[i];
    __syncthreads();

    int node = blockIdx.x * 256 + tid;
    if (node >= n_nodes) return;

    float a0 = bo[0], a1 = bo[1], a2 = bo[2];
    const float4* hv = reinterpret_cast<const float4*>(h + (size_t)node * HID);
#pragma unroll
    for (int kb = 0; kb < 25; ++kb) {
        float4 v = hv[kb];
        int k = kb * 4;
        a0 += v.x * sW[(k+0)*3+0]; a1 += v.x * sW[(k+0)*3+1]; a2 += v.x * sW[(k+0)*3+2];
        a0 += v.y * sW[(k+1)*3+0]; a1 += v.y * sW[(k+1)*3+1]; a2 += v.y * sW[(k+1)*3+2];
        a0 += v.z * sW[(k+2)*3+0]; a1 += v.z * sW[(k+2)*3+1]; a2 += v.z * sW[(k+2)*3+2];
        a0 += v.w * sW[(k+3)*3+0]; a1 += v.w * sW[(k+3)*3+1]; a2 += v.w * sW[(k+3)*3+2];
    }
    y[(size_t)node * 3 + 0] = 1.0f / (1.0f + expf(-a0));
    y[(size_t)node * 3 + 1] = 1.0f / (1.0f + expf(-a1));
    y[(size_t)node * 3 + 2] = 1.0f / (1.0f + expf(-a2));
}

// ---------------------------------------------------------------------------
extern "C" void kernel_launch(void* const* d_in, const int* in_sizes, int n_in,
                              void* d_out, int out_size)
{
    const float* x      = (const float*)d_in[0];
    const float* ef     = (const float*)d_in[1];
    const int*   src    = (const int*)  d_in[2];
    const int*   dst    = (const int*)  d_in[3];
    const float* W_lift = (const float*)d_in[4];
    const float* b_lift = (const float*)d_in[5];
    const float* W1     = (const float*)d_in[6];
    const float* b1     = (const float*)d_in[7];
    const float* W2     = (const float*)d_in[8];
    const float* b2     = (const float*)d_in[9];
    const float* W3     = (const float*)d_in[10];
    const float* b3     = (const float*)d_in[11];
    const float* W_out  = (const float*)d_in[12];
    const float* b_out  = (const float*)d_in[13];
    float* y = (float*)d_out;

    float *h, *h2, *red;
    __nv_bfloat16* Bg;
    cudaGetSymbolAddress((void**)&h,   g_h);
    cudaGetSymbolAddress((void**)&h2,  g_h2);
    cudaGetSymbolAddress((void**)&red, g_red);
    cudaGetSymbolAddress((void**)&Bg,  g_Bmma);

    const int GEMM_GRID = (N_NODES + 127) / 128;   // 782
    const size_t SMEM_LIFT = (IN_F * 128 + 128 * (IN_F + 4)) * sizeof(float);

    // 0) prep bf16 hi/lo weight images (once per launch)
    prep_B_kernel<<<(3 * KP * 128 + 255) / 256, 256>>>(W1, W2, W3);

    // 1) lift: h = tanh(x @ W_lift + b_lift)
    lift_gemm_kernel<IN_F><<<GEMM_GRID, 512, SMEM_LIFT>>>(x, W_lift, b_lift, h, N_NODES);

    const unsigned SCAT_GRID = ((unsigned)N_EDGES * 25u + 255u) / 256u;
    const size_t RED_BYTES = (size_t)N_NODES * HID * sizeof(float);

    const float* bs[3] = { b1, b2, b3 };
    float* bufs[4] = { h, h2, h, h2 };

    for (int l = 0; l < 3; ++l) {
        float* hin  = bufs[l];
        float* hout = bufs[l + 1];
        cudaMemsetAsync(red, 0, RED_BYTES);
        scatter_kernel<<<SCAT_GRID, 256>>>(hin, ef, src, dst, red);
        mpl_gemm_mma<<<GEMM_GRID, 512>>>(
            hin, red, Bg + (size_t)l * KP * 128, bs[l], hout, N_NODES);
    }

    // 3) output head
    out_kernel<<<(N_NODES + 255) / 256, 256>>>(h2, W_out, b_out, y, N_NODES);

    (void)in_sizes; (void)n_in; (void)out_size;
}

// round 5
// speedup vs baseline: 2.7812x; 1.1314x over previous
#include <cuda_runtime.h>
#include <cuda_bf16.h>
#include <math.h>
#include <stdint.h>

#define N_NODES 100000
#define N_EDGES 1600000
#define IN_F    16
#define HID     100
#define OUTF    3

// K' layout: 3 sections of 208 (200 real + 8 pad), total 624 = 39 x 16
// sections: 0 = A_hi (x) B_hi, 1 = A_lo (x) B_hi, 2 = A_hi (x) B_lo
#define SEC   208
#define KP    624
#define KC    48           // B streaming chunk (3 mma-k16 per chunk)
#define NCH   (KP / KC)    // 13

#define A_STR 632          // sA row stride (bf16 elems); 1264B -> ldmatrix conflict-free
#define B_STR 136          // sB row stride (bf16 elems); 272B  -> ldmatrix conflict-free
#define SB_BYTES (KC * B_STR * 2)          // 13056 per buffer
#define SA_BYTES (128 * A_STR * 2)         // 161792
#define SMEM_MMA (SA_BYTES + 2 * SB_BYTES) // 187904

// ---------------------------------------------------------------------------
// Scratch (device globals; allocation APIs are forbidden)
// ---------------------------------------------------------------------------
__device__ __align__(16) float g_h  [N_NODES * HID];
__device__ __align__(16) float g_h2 [N_NODES * HID];
__device__ __align__(16) float g_red[N_NODES * HID];
// Pre-built bf16 B' images: [layer(3)][kp(624)][col(128)]
__device__ __align__(16) __nv_bfloat16 g_Bmma[3 * KP * 128];

__device__ __forceinline__ uint32_t smem_u32(const void* p) {
    uint32_t a;
    asm("{ .reg .u64 t; cvta.to.shared.u64 t, %1; cvt.u32.u64 %0, t; }" : "=r"(a) : "l"(p));
    return a;
}

// ---------------------------------------------------------------------------
// Prep: B'[l][kp][col] where B = W^T (col = out-col, kk = in-dim)
// sections: 0 -> bf16_hi(W), 1 -> bf16_hi(W), 2 -> bf16_lo(W)
// ---------------------------------------------------------------------------
__global__ __launch_bounds__(256)
void prep_B_kernel(const float* __restrict__ W1, const float* __restrict__ W2,
                   const float* __restrict__ W3)
{
    int i = blockIdx.x * 256 + threadIdx.x;
    if (i >= 3 * KP * 128) return;
    int l   = i / (KP * 128);
    int r   = i - l * (KP * 128);
    int kp  = r >> 7;
    int col = r & 127;
    int sec = (kp >= 2 * SEC) ? 2 : (kp >= SEC ? 1 : 0);
    int kk  = kp - sec * SEC;

    const float* W = (l == 0) ? W1 : (l == 1) ? W2 : W3;
    float w = (kk < 2 * HID && col < HID) ? W[kk * HID + col] : 0.0f;

    __nv_bfloat16 hi = __float2bfloat16(w);
    __nv_bfloat16 o  = (sec == 2) ? __float2bfloat16(w - __bfloat162float(hi)) : hi;
    g_Bmma[i] = o;
}

// ---------------------------------------------------------------------------
// MPL GEMM via mma.sync m16n8k16 bf16, hi/lo split folded into K'=624.
// A' (128 x 624 bf16) is built ONCE into smem; B' streamed in 48-row chunks
// with cp.async double buffering. 512 thr = 16 warps (8 x M, 2 x N),
// warp tile 16 x 64, acc 8 frags x 4 f32 per thread.
// ---------------------------------------------------------------------------
__global__ __launch_bounds__(512, 1)
void mpl_gemm_mma(const float* __restrict__ h,
                  const float* __restrict__ red,
                  const __nv_bfloat16* __restrict__ Bg,  // layer base in g_Bmma
                  const float* __restrict__ b,
                  float* __restrict__ out,
                  int n_nodes)
{
    extern __shared__ __align__(16) uint8_t smem[];
    __nv_bfloat16* sA = reinterpret_cast<__nv_bfloat16*>(smem);
    const uint32_t sbase  = smem_u32(smem);
    const uint32_t sbBase = sbase + SA_BYTES;

    const int tid    = threadIdx.x;
    const int wid    = tid >> 5;
    const int lane   = tid & 31;
    const int warp_m = wid & 7;
    const int warp_n = wid >> 3;
    const int node0  = blockIdx.x * 128;

    // ---- prologue: prefetch B chunk 0 ----
    {
        const char* src = reinterpret_cast<const char*>(Bg);
        for (int i = tid; i < KC * 16; i += 512) {   // 768 x 16B
            int rowk = i >> 4;
            int c8   = (i & 15) << 3;
            uint32_t dst = sbBase + (uint32_t)((rowk * B_STR + c8) * 2);
            asm volatile("cp.async.cg.shared.global [%0], [%1], 16;"
                         :: "r"(dst), "l"(src + i * 16) : "memory");
        }
        asm volatile("cp.async.commit_group;" ::: "memory");
    }

    // ---- fill A' once: v -> hi (sec 0 and 2... note: secs 0,2 = hi; 1 = lo) ----
    // section roles must match B': B sec0=hi,sec1=hi,sec2=lo; product terms:
    //   sec0: A_hi*B_hi, sec1: A_lo*B_hi, sec2: A_hi*B_lo
    for (int i = tid; i < 128 * SEC; i += 512) {
        int row = i / SEC;
        int kk  = i - row * SEC;
        int n   = node0 + row;
        float v = 0.0f;
        if (n < n_nodes) {
            if (kk < HID)          v = h[n * HID + kk];
            else if (kk < 2 * HID) v = red[n * HID + kk - HID];
        }
        __nv_bfloat16 hi = __float2bfloat16(v);
        __nv_bfloat16 lo = __float2bfloat16(v - __bfloat162float(hi));
        __nv_bfloat16* rp = sA + row * A_STR;
        rp[kk]           = hi;
        rp[SEC + kk]     = lo;
        rp[2 * SEC + kk] = hi;
    }

    float acc[8][4];
#pragma unroll
    for (int f = 0; f < 8; ++f)
#pragma unroll
        for (int j = 0; j < 4; ++j) acc[f][j] = 0.0f;

    // ldmatrix lane addressing (canonical m16n8k16 pattern)
    const int lrow  = lane & 15;
    const int lkoff = (lane >> 4) << 3;
    const uint32_t aBase = sbase + (uint32_t)(((warp_m * 16 + lrow) * A_STR + lkoff) * 2);
    const uint32_t bOff  = (uint32_t)((lrow * B_STR + warp_n * 64 + lkoff) * 2);

    for (int ch = 0; ch < NCH; ++ch) {
        asm volatile("cp.async.wait_group 0;" ::: "memory");
        __syncthreads();   // chunk ch ready; all warps done with buf[(ch)&1]'s previous use

        // prefetch chunk ch+1 into the other buffer
        if (ch + 1 < NCH) {
            const char* src = reinterpret_cast<const char*>(Bg + (size_t)(ch + 1) * KC * 128);
            uint32_t dbuf = sbBase + (uint32_t)(((ch + 1) & 1) * SB_BYTES);
            for (int i = tid; i < KC * 16; i += 512) {
                int rowk = i >> 4;
                int c8   = (i & 15) << 3;
                uint32_t dst = dbuf + (uint32_t)((rowk * B_STR + c8) * 2);
                asm volatile("cp.async.cg.shared.global [%0], [%1], 16;"
                             :: "r"(dst), "l"(src + i * 16) : "memory");
            }
            asm volatile("cp.async.commit_group;" ::: "memory");
        }

        const uint32_t bBase = sbBase + (uint32_t)((ch & 1) * SB_BYTES) + bOff;
        const uint32_t aCh   = aBase + (uint32_t)(ch * KC * 2);
#pragma unroll
        for (int kf = 0; kf < KC / 16; ++kf) {
            uint32_t a0, a1, a2, a3;
            asm volatile("ldmatrix.sync.aligned.m8n8.x4.shared.b16 {%0,%1,%2,%3}, [%4];"
                         : "=r"(a0), "=r"(a1), "=r"(a2), "=r"(a3)
                         : "r"(aCh + (uint32_t)(kf * 16 * 2)));
#pragma unroll
            for (int nb = 0; nb < 4; ++nb) {
                uint32_t b0, b1, b2, b3;
                asm volatile("ldmatrix.sync.aligned.m8n8.x4.trans.shared.b16 {%0,%1,%2,%3}, [%4];"
                             : "=r"(b0), "=r"(b1), "=r"(b2), "=r"(b3)
                             : "r"(bBase + (uint32_t)((kf * 16 * B_STR + nb * 16) * 2)));
                asm volatile("mma.sync.aligned.m16n8k16.row.col.f32.bf16.bf16.f32 "
                             "{%0,%1,%2,%3}, {%4,%5,%6,%7}, {%8,%9}, {%0,%1,%2,%3};"
                             : "+f"(acc[nb * 2][0]), "+f"(acc[nb * 2][1]),
                               "+f"(acc[nb * 2][2]), "+f"(acc[nb * 2][3])
                             : "r"(a0), "r"(a1), "r"(a2), "r"(a3), "r"(b0), "r"(b1));
                asm volatile("mma.sync.aligned.m16n8k16.row.col.f32.bf16.bf16.f32 "
                             "{%0,%1,%2,%3}, {%4,%5,%6,%7}, {%8,%9}, {%0,%1,%2,%3};"
                             : "+f"(acc[nb * 2 + 1][0]), "+f"(acc[nb * 2 + 1][1]),
                               "+f"(acc[nb * 2 + 1][2]), "+f"(acc[nb * 2 + 1][3])
                             : "r"(a0), "r"(a1), "r"(a2), "r"(a3), "r"(b2), "r"(b3));
            }
        }
    }

    // ---- epilogue: bias + relu + float2 stores ----
    const int gr = lane >> 2;
    const int tc = lane & 3;
    const int r0 = node0 + warp_m * 16 + gr;
    const int r1 = r0 + 8;
#pragma unroll
    for (int f = 0; f < 8; ++f) {
        int col = warp_n * 64 + f * 8 + tc * 2;
        if (col < HID) {
            float b0 = b[col], b1 = b[col + 1];
            if (r0 < n_nodes) {
                float2 v;
                v.x = fmaxf(acc[f][0] + b0, 0.f);
                v.y = fmaxf(acc[f][1] + b1, 0.f);
                *reinterpret_cast<float2*>(out + (size_t)r0 * HID + col) = v;
            }
            if (r1 < n_nodes) {
                float2 v;
                v.x = fmaxf(acc[f][2] + b0, 0.f);
                v.y = fmaxf(acc[f][3] + b1, 0.f);
                *reinterpret_cast<float2*>(out + (size_t)r1 * HID + col) = v;
            }
        }
    }
}

// ---------------------------------------------------------------------------
// Lift GEMM (FFMA; tiny K=16): h = tanh(x @ W_lift + b_lift)
// ---------------------------------------------------------------------------
template <int KDIM>
__global__ __launch_bounds__(512, 1)
void lift_gemm_kernel(const float* __restrict__ in1,
                      const float* __restrict__ W,
                      const float* __restrict__ b,
                      float* __restrict__ out,
                      int n_nodes)
{
    extern __shared__ float sm[];
    constexpr int SSTR = KDIM + 4;
    float* sW  = sm;
    float* sIn = sm + KDIM * 128;

    const int tid   = threadIdx.x;
    const int node0 = blockIdx.x * 128;

    for (int i = tid; i < KDIM * 128; i += 512) {
        int k = i >> 7, c = i & 127;
        sW[i] = (c < HID) ? W[k * HID + c] : 0.0f;
    }
    for (int i = tid; i < 128 * KDIM; i += 512) {
        int nl = i / KDIM, k = i - nl * KDIM;
        int n  = node0 + nl;
        sIn[nl * SSTR + k] = (n < n_nodes) ? in1[n * KDIM + k] : 0.0f;
    }
    __syncthreads();

    const int lane = tid & 31;
    const int wp   = tid >> 5;
    const float* abase = sIn + wp * 8 * SSTR;
    const float* wbase = sW + lane * 4;

    float4 acc[8];
#pragma unroll
    for (int j = 0; j < 8; ++j) acc[j] = make_float4(0.f, 0.f, 0.f, 0.f);

#pragma unroll
    for (int k0 = 0; k0 < KDIM; k0 += 4) {
        const float4 w0 = *reinterpret_cast<const float4*>(wbase + (k0 + 0) * 128);
        const float4 w1 = *reinterpret_cast<const float4*>(wbase + (k0 + 1) * 128);
        const float4 w2 = *reinterpret_cast<const float4*>(wbase + (k0 + 2) * 128);
        const float4 w3 = *reinterpret_cast<const float4*>(wbase + (k0 + 3) * 128);
#pragma unroll
        for (int j = 0; j < 8; ++j) {
            const float4 a = *reinterpret_cast<const float4*>(abase + j * SSTR + k0);
            acc[j].x += a.x * w0.x; acc[j].y += a.x * w0.y; acc[j].z += a.x * w0.z; acc[j].w += a.x * w0.w;
            acc[j].x += a.y * w1.x; acc[j].y += a.y * w1.y; acc[j].z += a.y * w1.z; acc[j].w += a.y * w1.w;
            acc[j].x += a.z * w2.x; acc[j].y += a.z * w2.y; acc[j].z += a.z * w2.z; acc[j].w += a.z * w2.w;
            acc[j].x += a.w * w3.x; acc[j].y += a.w * w3.y; acc[j].z += a.w * w3.z; acc[j].w += a.w * w3.w;
        }
    }

    if (lane < 25) {
        const float4 bias = *reinterpret_cast<const float4*>(b + lane * 4);
#pragma unroll
        for (int j = 0; j < 8; ++j) {
            int n = node0 + wp * 8 + j;
            if (n < n_nodes) {
                float4 r;
                r.x = tanhf(acc[j].x + bias.x); r.y = tanhf(acc[j].y + bias.y);
                r.z = tanhf(acc[j].z + bias.z); r.w = tanhf(acc[j].w + bias.w);
                *reinterpret_cast<float4*>(out + (size_t)n * HID + lane * 4) = r;
            }
        }
    }
}

// ---------------------------------------------------------------------------
// Edge scatter: reduced[dst] += edge_w * h[src]
// ---------------------------------------------------------------------------
__global__ __launch_bounds__(256)
void scatter_kernel(const float* __restrict__ h,
                    const float* __restrict__ ef,
                    const int*   __restrict__ src,
                    const int*   __restrict__ dst,
                    float* __restrict__ red)
{
    unsigned idx = blockIdx.x * 256u + threadIdx.x;
    if (idx >= (unsigned)N_EDGES * 25u) return;
    unsigned e = idx / 25u;
    unsigned c = idx - e * 25u;

    float w = ef[e];
    int   s = src[e];
    int   d = dst[e];

    const float4 v = *reinterpret_cast<const float4*>(h + (size_t)s * HID + c * 4u);
    float* p = red + (size_t)d * HID + c * 4u;
    asm volatile("red.global.add.v4.f32 [%0], {%1, %2, %3, %4};"
                 :: "l"(p), "f"(v.x * w), "f"(v.y * w), "f"(v.z * w), "f"(v.w * w)
                 : "memory");
}

// ---------------------------------------------------------------------------
// Output head: y[n] = sigmoid(h[n,0:100] @ W_out[100x3] + b_out)
// ---------------------------------------------------------------------------
__global__ __launch_bounds__(256)
void out_kernel(const float* __restrict__ h,
                const float* __restrict__ Wo,
                const float* __restrict__ bo,
                float* __restrict__ y,
                int n_nodes)
{
    __shared__ float sW[HID * OUTF];
    int tid = threadIdx.x;
    for (int i = tid; i < HID * OUTF; i += 256) sW[i] = Wo[i];
    __syncthreads();

    int node = blockIdx.x * 256 + tid;
    if (node >= n_nodes) return;

    float a0 = bo[0], a1 = bo[1], a2 = bo[2];
    const float4* hv = reinterpret_cast<const float4*>(h + (size_t)node * HID);
#pragma unroll
    for (int kb = 0; kb < 25; ++kb) {
        float4 v = hv[kb];
        int k = kb * 4;
        a0 += v.x * sW[(k+0)*3+0]; a1 += v.x * sW[(k+0)*3+1]; a2 += v.x * sW[(k+0)*3+2];
        a0 += v.y * sW[(k+1)*3+0]; a1 += v.y * sW[(k+1)*3+1]; a2 += v.y * sW[(k+1)*3+2];
        a0 += v.z * sW[(k+2)*3+0]; a1 += v.z * sW[(k+2)*3+1]; a2 += v.z * sW[(k+2)*3+2];
        a0 += v.w * sW[(k+3)*3+0]; a1 += v.w * sW[(k+3)*3+1]; a2 += v.w * sW[(k+3)*3+2];
    }
    y[(size_t)node * 3 + 0] = 1.0f / (1.0f + expf(-a0));
    y[(size_t)node * 3 + 1] = 1.0f / (1.0f + expf(-a1));
    y[(size_t)node * 3 + 2] = 1.0f / (1.0f + expf(-a2));
}

// ---------------------------------------------------------------------------
extern "C" void kernel_launch(void* const* d_in, const int* in_sizes, int n_in,
                              void* d_out, int out_size)
{
    const float* x      = (const float*)d_in[0];
    const float* ef     = (const float*)d_in[1];
    const int*   src    = (const int*)  d_in[2];
    const int*   dst    = (const int*)  d_in[3];
    const float* W_lift = (const float*)d_in[4];
    const float* b_lift = (const float*)d_in[5];
    const float* W1     = (const float*)d_in[6];
    const float* b1     = (const float*)d_in[7];
    const float* W2     = (const float*)d_in[8];
    const float* b2     = (const float*)d_in[9];
    const float* W3     = (const float*)d_in[10];
    const float* b3     = (const float*)d_in[11];
    const float* W_out  = (const float*)d_in[12];
    const float* b_out  = (const float*)d_in[13];
    float* y = (float*)d_out;

    float *h, *h2, *red;
    __nv_bfloat16* Bg;
    cudaGetSymbolAddress((void**)&h,   g_h);
    cudaGetSymbolAddress((void**)&h2,  g_h2);
    cudaGetSymbolAddress((void**)&red, g_red);
    cudaGetSymbolAddress((void**)&Bg,  g_Bmma);

    const int GEMM_GRID = (N_NODES + 127) / 128;   // 782
    const size_t SMEM_LIFT = (IN_F * 128 + 128 * (IN_F + 4)) * sizeof(float);

    cudaFuncSetAttribute((const void*)mpl_gemm_mma,
                         cudaFuncAttributeMaxDynamicSharedMemorySize, SMEM_MMA);

    // 0) prep bf16 hi/lo weight images (once per launch)
    prep_B_kernel<<<(3 * KP * 128 + 255) / 256, 256>>>(W1, W2, W3);

    // 1) lift
    lift_gemm_kernel<IN_F><<<GEMM_GRID, 512, SMEM_LIFT>>>(x, W_lift, b_lift, h, N_NODES);

    const unsigned SCAT_GRID = ((unsigned)N_EDGES * 25u + 255u) / 256u;
    const size_t RED_BYTES = (size_t)N_NODES * HID * sizeof(float);

    const float* bs[3] = { b1, b2, b3 };
    float* bufs[4] = { h, h2, h, h2 };

    for (int l = 0; l < 3; ++l) {
        float* hin  = bufs[l];
        float* hout = bufs[l + 1];
        cudaMemsetAsync(red, 0, RED_BYTES);
        scatter_kernel<<<SCAT_GRID, 256>>>(hin, ef, src, dst, red);
        mpl_gemm_mma<<<GEMM_GRID, 512, SMEM_MMA>>>(
            hin, red, Bg + (size_t)l * KP * 128, bs[l], hout, N_NODES);
    }

    // 3) output head
    out_kernel<<<(N_NODES + 255) / 256, 256>>>(h2, W_out, b_out, y, N_NODES);

    (void)in_sizes; (void)n_in; (void)out_size;
}

// round 6
// speedup vs baseline: 3.1969x; 1.1495x over previous
#include <cuda_runtime.h>
#include <cuda_bf16.h>
#include <math.h>
#include <stdint.h>

#define N_NODES 100000
#define N_EDGES 1600000
#define IN_F    16
#define HID     100
#define OUTF    3

// K' = 3 sections x 208 (200 real + 8 pad) = 624 = 39 x k16
// product terms: sec0 = A_hi*B_hi, sec1 = A_lo*B_hi, sec2 = A_hi*B_lo
// A smem stores only hi(208) + lo(208); sec2 re-reads the hi region.
#define SEC    208
#define NKF    39         // 39 k16 steps
#define MT     96         // nodes per CTA
#define THR    384        // 12 warps: 6 along M x 2 along N
#define A_STR  424        // bf16 elems per sA row (848B, ldmatrix conflict-free)
#define SA_BYTES (MT * A_STR * 2)   // 81408

// ---------------------------------------------------------------------------
// Scratch (device globals; allocation APIs are forbidden)
// ---------------------------------------------------------------------------
__device__ __align__(16) float g_h  [N_NODES * HID];
__device__ __align__(16) float g_h2 [N_NODES * HID];
__device__ __align__(16) float g_red[N_NODES * HID];
// B' packed in m16n8k16 B-fragment order:
// [layer(3)][kf(39)][warp_n(2)][nbp(4)][lane(32)] x uint4
// uint4 = {b0(nb=2*nbp), b1(nb), b0(nb+1), b1(nb+1)}
__device__ __align__(16) uint4 g_Bfrag[3 * NKF * 2 * 4 * 32];

__device__ __forceinline__ uint32_t smem_u32(const void* p) {
    uint32_t a;
    asm("{ .reg .u64 t; cvta.to.shared.u64 t, %1; cvt.u32.u64 %0, t; }" : "=r"(a) : "l"(p));
    return a;
}
__device__ __forceinline__ uint32_t bf2_u32(__nv_bfloat162 v) {
    return *reinterpret_cast<uint32_t*>(&v);
}

// ---------------------------------------------------------------------------
// Prep: pack B' (= W^T with hi/hi/lo sections) into MMA B-fragment layout.
// One thread per output uint4 (3*39*2*4*32 = 29952).
// ---------------------------------------------------------------------------
__device__ __forceinline__ __nv_bfloat16 wconv(const float* W, int sec, int kk, int col) {
    float w = (kk < 2 * HID && col < HID) ? W[kk * HID + col] : 0.0f;
    __nv_bfloat16 hi = __float2bfloat16(w);
    return (sec == 2) ? __float2bfloat16(w - __bfloat162float(hi)) : hi;
}

__global__ __launch_bounds__(256)
void prep_B_kernel(const float* __restrict__ W1, const float* __restrict__ W2,
                   const float* __restrict__ W3)
{
    int i = blockIdx.x * 256 + threadIdx.x;
    if (i >= 3 * NKF * 2 * 4 * 32) return;
    int l    = i / (NKF * 256);
    int r    = i - l * (NKF * 256);
    int kf   = r >> 8;
    int r2   = r & 255;
    int wn   = r2 >> 7;
    int nbp  = (r2 >> 5) & 3;
    int lane = r2 & 31;

    int sec = kf / 13;
    int kk0 = (kf - sec * 13) * 16 + (lane & 3) * 2;   // within section
    int n0  = wn * 64 + (nbp * 2) * 8 + (lane >> 2);
    int n1  = n0 + 8;

    const float* W = (l == 0) ? W1 : (l == 1) ? W2 : W3;

    uint4 o;
    o.x = bf2_u32(__nv_bfloat162(wconv(W, sec, kk0,     n0), wconv(W, sec, kk0 + 1, n0)));
    o.y = bf2_u32(__nv_bfloat162(wconv(W, sec, kk0 + 8, n0), wconv(W, sec, kk0 + 9, n0)));
    o.z = bf2_u32(__nv_bfloat162(wconv(W, sec, kk0,     n1), wconv(W, sec, kk0 + 1, n1)));
    o.w = bf2_u32(__nv_bfloat162(wconv(W, sec, kk0 + 8, n1), wconv(W, sec, kk0 + 9, n1)));
    g_Bfrag[i] = o;
}

// ---------------------------------------------------------------------------
// MPL GEMM: out[n,0:100] = relu( concat(h[n], red[n]) @ W + b )
// A' (96 x 416 bf16 hi/lo) resident in smem (filled once, one sync);
// B' fragments LDG.128 direct from gmem (L1-resident) -> no mainloop syncs.
// 12 warps: warp tile 16 x 64; acc 8 frags x 4 f32.
// ---------------------------------------------------------------------------
__global__ __launch_bounds__(THR, 2)
void mpl_gemm_mma(const float* __restrict__ h,
                  const float* __restrict__ red,
                  const uint4* __restrict__ Bf,   // layer base in g_Bfrag
                  const float* __restrict__ b,
                  float* __restrict__ out,
                  int n_nodes)
{
    extern __shared__ __align__(16) uint8_t smem[];
    __nv_bfloat16* sA = reinterpret_cast<__nv_bfloat16*>(smem);
    const uint32_t sbase = smem_u32(smem);

    const int tid    = threadIdx.x;
    const int wid    = tid >> 5;
    const int lane   = tid & 31;
    const int warp_m = wid >> 1;         // 0..5
    const int warp_n = wid & 1;          // 0..1
    const int node0  = blockIdx.x * MT;

    // ---- fill A' once (vectorized): hi at [0,208), lo at [208,416) ----
    for (int i = tid; i < MT * 52; i += THR) {
        int row = i / 52;
        int kk  = (i - row * 52) * 4;
        int n   = node0 + row;
        float4 v = make_float4(0.f, 0.f, 0.f, 0.f);
        if (n < n_nodes) {
            if (kk < HID)          v = *reinterpret_cast<const float4*>(h + (size_t)n * HID + kk);
            else if (kk < 2 * HID) v = *reinterpret_cast<const float4*>(red + (size_t)n * HID + kk - HID);
        }
        __nv_bfloat162 h0 = __floats2bfloat162_rn(v.x, v.y);
        __nv_bfloat162 h1 = __floats2bfloat162_rn(v.z, v.w);
        __nv_bfloat162 l0 = __floats2bfloat162_rn(v.x - __bfloat162float(h0.x),
                                                  v.y - __bfloat162float(h0.y));
        __nv_bfloat162 l1 = __floats2bfloat162_rn(v.z - __bfloat162float(h1.x),
                                                  v.w - __bfloat162float(h1.y));
        __nv_bfloat16* rp = sA + row * A_STR;
        *reinterpret_cast<uint2*>(rp + kk)       = make_uint2(bf2_u32(h0), bf2_u32(h1));
        *reinterpret_cast<uint2*>(rp + SEC + kk) = make_uint2(bf2_u32(l0), bf2_u32(l1));
    }
    __syncthreads();

    float acc[8][4];
#pragma unroll
    for (int f = 0; f < 8; ++f)
#pragma unroll
        for (int j = 0; j < 4; ++j) acc[f][j] = 0.0f;

    const int lrow  = lane & 15;
    const int lkoff = (lane >> 4) << 3;
    const uint32_t aPtr = sbase + (uint32_t)(((warp_m * 16 + lrow) * A_STR + lkoff) * 2);
    const uint4* bp0 = Bf + (size_t)warp_n * 128 + lane;   // +kf*256, +nbp*32

#pragma unroll
    for (int sec = 0; sec < 3; ++sec) {
        const uint32_t abase = aPtr + (uint32_t)((sec == 1 ? SEC : 0) * 2);
#pragma unroll
        for (int k13 = 0; k13 < 13; ++k13) {
            uint32_t a0, a1, a2, a3;
            asm volatile("ldmatrix.sync.aligned.m8n8.x4.shared.b16 {%0,%1,%2,%3}, [%4];"
                         : "=r"(a0), "=r"(a1), "=r"(a2), "=r"(a3)
                         : "r"(abase + (uint32_t)(k13 * 32)));
            const uint4* bp = bp0 + (size_t)(sec * 13 + k13) * 256;
#pragma unroll
            for (int nbp = 0; nbp < 4; ++nbp) {
                const uint4 bv = bp[nbp * 32];
                asm volatile("mma.sync.aligned.m16n8k16.row.col.f32.bf16.bf16.f32 "
                             "{%0,%1,%2,%3}, {%4,%5,%6,%7}, {%8,%9}, {%0,%1,%2,%3};"
                             : "+f"(acc[nbp * 2][0]), "+f"(acc[nbp * 2][1]),
                               "+f"(acc[nbp * 2][2]), "+f"(acc[nbp * 2][3])
                             : "r"(a0), "r"(a1), "r"(a2), "r"(a3), "r"(bv.x), "r"(bv.y));
                asm volatile("mma.sync.aligned.m16n8k16.row.col.f32.bf16.bf16.f32 "
                             "{%0,%1,%2,%3}, {%4,%5,%6,%7}, {%8,%9}, {%0,%1,%2,%3};"
                             : "+f"(acc[nbp * 2 + 1][0]), "+f"(acc[nbp * 2 + 1][1]),
                               "+f"(acc[nbp * 2 + 1][2]), "+f"(acc[nbp * 2 + 1][3])
                             : "r"(a0), "r"(a1), "r"(a2), "r"(a3), "r"(bv.z), "r"(bv.w));
            }
        }
    }

    // ---- epilogue: bias + relu + float2 stores ----
    const int gr = lane >> 2;
    const int tc = lane & 3;
    const int r0 = node0 + warp_m * 16 + gr;
    const int r1 = r0 + 8;
#pragma unroll
    for (int f = 0; f < 8; ++f) {
        int col = warp_n * 64 + f * 8 + tc * 2;
        if (col < HID) {
            float b0 = b[col], b1 = b[col + 1];
            if (r0 < n_nodes) {
                float2 v;
                v.x = fmaxf(acc[f][0] + b0, 0.f);
                v.y = fmaxf(acc[f][1] + b1, 0.f);
                *reinterpret_cast<float2*>(out + (size_t)r0 * HID + col) = v;
            }
            if (r1 < n_nodes) {
                float2 v;
                v.x = fmaxf(acc[f][2] + b0, 0.f);
                v.y = fmaxf(acc[f][3] + b1, 0.f);
                *reinterpret_cast<float2*>(out + (size_t)r1 * HID + col) = v;
            }
        }
    }
}

// ---------------------------------------------------------------------------
// Lift GEMM (FFMA; tiny K=16): h = tanh(x @ W_lift + b_lift)
// ---------------------------------------------------------------------------
template <int KDIM>
__global__ __launch_bounds__(512, 1)
void lift_gemm_kernel(const float* __restrict__ in1,
                      const float* __restrict__ W,
                      const float* __restrict__ b,
                      float* __restrict__ out,
                      int n_nodes)
{
    extern __shared__ float sm[];
    constexpr int SSTR = KDIM + 4;
    float* sW  = sm;
    float* sIn = sm + KDIM * 128;

    const int tid   = threadIdx.x;
    const int node0 = blockIdx.x * 128;

    for (int i = tid; i < KDIM * 128; i += 512) {
        int k = i >> 7, c = i & 127;
        sW[i] = (c < HID) ? W[k * HID + c] : 0.0f;
    }
    for (int i = tid; i < 128 * KDIM; i += 512) {
        int nl = i / KDIM, k = i - nl * KDIM;
        int n  = node0 + nl;
        sIn[nl * SSTR + k] = (n < n_nodes) ? in1[n * KDIM + k] : 0.0f;
    }
    __syncthreads();

    const int lane = tid & 31;
    const int wp   = tid >> 5;
    const float* abase = sIn + wp * 8 * SSTR;
    const float* wbase = sW + lane * 4;

    float4 acc[8];
#pragma unroll
    for (int j = 0; j < 8; ++j) acc[j] = make_float4(0.f, 0.f, 0.f, 0.f);

#pragma unroll
    for (int k0 = 0; k0 < KDIM; k0 += 4) {
        const float4 w0 = *reinterpret_cast<const float4*>(wbase + (k0 + 0) * 128);
        const float4 w1 = *reinterpret_cast<const float4*>(wbase + (k0 + 1) * 128);
        const float4 w2 = *reinterpret_cast<const float4*>(wbase + (k0 + 2) * 128);
        const float4 w3 = *reinterpret_cast<const float4*>(wbase + (k0 + 3) * 128);
#pragma unroll
        for (int j = 0; j < 8; ++j) {
            const float4 a = *reinterpret_cast<const float4*>(abase + j * SSTR + k0);
            acc[j].x += a.x * w0.x; acc[j].y += a.x * w0.y; acc[j].z += a.x * w0.z; acc[j].w += a.x * w0.w;
            acc[j].x += a.y * w1.x; acc[j].y += a.y * w1.y; acc[j].z += a.y * w1.z; acc[j].w += a.y * w1.w;
            acc[j].x += a.z * w2.x; acc[j].y += a.z * w2.y; acc[j].z += a.z * w2.z; acc[j].w += a.z * w2.w;
            acc[j].x += a.w * w3.x; acc[j].y += a.w * w3.y; acc[j].z += a.w * w3.z; acc[j].w += a.w * w3.w;
        }
    }

    if (lane < 25) {
        const float4 bias = *reinterpret_cast<const float4*>(b + lane * 4);
#pragma unroll
        for (int j = 0; j < 8; ++j) {
            int n = node0 + wp * 8 + j;
            if (n < n_nodes) {
                float4 r;
                r.x = tanhf(acc[j].x + bias.x); r.y = tanhf(acc[j].y + bias.y);
                r.z = tanhf(acc[j].z + bias.z); r.w = tanhf(acc[j].w + bias.w);
                *reinterpret_cast<float4*>(out + (size_t)n * HID + lane * 4) = r;
            }
        }
    }
}

// ---------------------------------------------------------------------------
// Edge scatter: reduced[dst] += edge_w * h[src]
// ---------------------------------------------------------------------------
__global__ __launch_bounds__(256)
void scatter_kernel(const float* __restrict__ h,
                    const float* __restrict__ ef,
                    const int*   __restrict__ src,
                    const int*   __restrict__ dst,
                    float* __restrict__ red)
{
    unsigned idx = blockIdx.x * 256u + threadIdx.x;
    if (idx >= (unsigned)N_EDGES * 25u) return;
    unsigned e = idx / 25u;
    unsigned c = idx - e * 25u;

    float w = ef[e];
    int   s = src[e];
    int   d = dst[e];

    const float4 v = *reinterpret_cast<const float4*>(h + (size_t)s * HID + c * 4u);
    float* p = red + (size_t)d * HID + c * 4u;
    asm volatile("red.global.add.v4.f32 [%0], {%1, %2, %3, %4};"
                 :: "l"(p), "f"(v.x * w), "f"(v.y * w), "f"(v.z * w), "f"(v.w * w)
                 : "memory");
}

// ---------------------------------------------------------------------------
// Output head: y[n] = sigmoid(h[n,0:100] @ W_out[100x3] + b_out)
// ---------------------------------------------------------------------------
__global__ __launch_bounds__(256)
void out_kernel(const float* __restrict__ h,
                const float* __restrict__ Wo,
                const float* __restrict__ bo,
                float* __restrict__ y,
                int n_nodes)
{
    __shared__ float sW[HID * OUTF];
    int tid = threadIdx.x;
    for (int i = tid; i < HID * OUTF; i += 256) sW[i] = Wo[i];
    __syncthreads();

    int node = blockIdx.x * 256 + tid;
    if (node >= n_nodes) return;

    float a0 = bo[0], a1 = bo[1], a2 = bo[2];
    const float4* hv = reinterpret_cast<const float4*>(h + (size_t)node * HID);
#pragma unroll
    for (int kb = 0; kb < 25; ++kb) {
        float4 v = hv[kb];
        int k = kb * 4;
        a0 += v.x * sW[(k+0)*3+0]; a1 += v.x * sW[(k+0)*3+1]; a2 += v.x * sW[(k+0)*3+2];
        a0 += v.y * sW[(k+1)*3+0]; a1 += v.y * sW[(k+1)*3+1]; a2 += v.y * sW[(k+1)*3+2];
        a0 += v.z * sW[(k+2)*3+0]; a1 += v.z * sW[(k+2)*3+1]; a2 += v.z * sW[(k+2)*3+2];
        a0 += v.w * sW[(k+3)*3+0]; a1 += v.w * sW[(k+3)*3+1]; a2 += v.w * sW[(k+3)*3+2];
    }
    y[(size_t)node * 3 + 0] = 1.0f / (1.0f + expf(-a0));
    y[(size_t)node * 3 + 1] = 1.0f / (1.0f + expf(-a1));
    y[(size_t)node * 3 + 2] = 1.0f / (1.0f + expf(-a2));
}

// ---------------------------------------------------------------------------
extern "C" void kernel_launch(void* const* d_in, const int* in_sizes, int n_in,
                              void* d_out, int out_size)
{
    const float* x      = (const float*)d_in[0];
    const float* ef     = (const float*)d_in[1];
    const int*   src    = (const int*)  d_in[2];
    const int*   dst    = (const int*)  d_in[3];
    const float* W_lift = (const float*)d_in[4];
    const float* b_lift = (const float*)d_in[5];
    const float* W1     = (const float*)d_in[6];
    const float* b1     = (const float*)d_in[7];
    const float* W2     = (const float*)d_in[8];
    const float* b2     = (const float*)d_in[9];
    const float* W3     = (const float*)d_in[10];
    const float* b3     = (const float*)d_in[11];
    const float* W_out  = (const float*)d_in[12];
    const float* b_out  = (const float*)d_in[13];
    float* y = (float*)d_out;

    float *h, *h2, *red;
    uint4* Bf;
    cudaGetSymbolAddress((void**)&h,   g_h);
    cudaGetSymbolAddress((void**)&h2,  g_h2);
    cudaGetSymbolAddress((void**)&red, g_red);
    cudaGetSymbolAddress((void**)&Bf,  g_Bfrag);

    const size_t SMEM_LIFT = (IN_F * 128 + 128 * (IN_F + 4)) * sizeof(float);

    cudaFuncSetAttribute((const void*)mpl_gemm_mma,
                         cudaFuncAttributeMaxDynamicSharedMemorySize, SA_BYTES);

    // 0) prep B fragments (once per launch)
    prep_B_kernel<<<(3 * NKF * 256 + 255) / 256, 256>>>(W1, W2, W3);

    // 1) lift
    lift_gemm_kernel<IN_F><<<(N_NODES + 127) / 128, 512, SMEM_LIFT>>>(
        x, W_lift, b_lift, h, N_NODES);

    const unsigned SCAT_GRID = ((unsigned)N_EDGES * 25u + 255u) / 256u;
    const size_t RED_BYTES = (size_t)N_NODES * HID * sizeof(float);
    const int MPL_GRID = (N_NODES + MT - 1) / MT;   // 1042

    const float* bs[3] = { b1, b2, b3 };
    float* bufs[4] = { h, h2, h, h2 };

    for (int l = 0; l < 3; ++l) {
        float* hin  = bufs[l];
        float* hout = bufs[l + 1];
        cudaMemsetAsync(red, 0, RED_BYTES);
        scatter_kernel<<<SCAT_GRID, 256>>>(hin, ef, src, dst, red);
        mpl_gemm_mma<<<MPL_GRID, THR, SA_BYTES>>>(
            hin, red, Bf + (size_t)l * NKF * 256, bs[l], hout, N_NODES);
    }

    // 3) output head
    out_kernel<<<(N_NODES + 255) / 256, 256>>>(h2, W_out, b_out, y, N_NODES);

    (void)in_sizes; (void)n_in; (void)out_size;
}

// round 7
// speedup vs baseline: 4.4015x; 1.3768x over previous
#include <cuda_runtime.h>
#include <cuda_bf16.h>
#include <math.h>
#include <stdint.h>

#define N_NODES 100000
#define N_EDGES 1600000
#define IN_F    16
#define HID     100
#define OUTF    3

// K' = 3 sections x 208 (200 real + 8 pad) = 624 = 39 x k16
// product terms: sec0 = A_hi*B_hi, sec1 = A_lo*B_hi, sec2 = A_hi*B_lo
#define SEC    208
#define NKF    39
#define MT     96
#define THR    384
#define A_STR  424
#define SA_BYTES (MT * A_STR * 2)   // 81408

#define SCAN_B 1024
#define NBLK   ((N_NODES + SCAN_B - 1) / SCAN_B)   // 98

// ---------------------------------------------------------------------------
// Scratch (device globals; allocation APIs are forbidden)
// ---------------------------------------------------------------------------
__device__ __align__(16) float g_h  [N_NODES * HID];
__device__ __align__(16) float g_h2 [N_NODES * HID];
__device__ __align__(16) float g_red[N_NODES * HID];
__device__ __align__(16) uint4 g_Bfrag[3 * NKF * 2 * 4 * 32];
// CSR scratch
__device__ int   g_cnt   [N_NODES];
__device__ int   g_rowptr[N_NODES + 1];
__device__ int   g_cur   [N_NODES];
__device__ int   g_bsum  [NBLK];
__device__ int   g_bsumex[NBLK];
__device__ __align__(16) uint2 g_edge[N_EDGES];   // {src, w bits} sorted by dst

__device__ __forceinline__ uint32_t smem_u32(const void* p) {
    uint32_t a;
    asm("{ .reg .u64 t; cvta.to.shared.u64 t, %1; cvt.u32.u64 %0, t; }" : "=r"(a) : "l"(p));
    return a;
}
__device__ __forceinline__ uint32_t bf2_u32(__nv_bfloat162 v) {
    return *reinterpret_cast<uint32_t*>(&v);
}

// ---------------------------------------------------------------------------
// CSR build
// ---------------------------------------------------------------------------
__global__ __launch_bounds__(256)
void hist_kernel(const int* __restrict__ dst) {
    int e = blockIdx.x * 256 + threadIdx.x;
    if (e < N_EDGES) atomicAdd(&g_cnt[dst[e]], 1);
}

__global__ __launch_bounds__(SCAN_B)
void block_sum_kernel() {
    __shared__ int s[SCAN_B];
    int i = blockIdx.x * SCAN_B + threadIdx.x;
    s[threadIdx.x] = (i < N_NODES) ? g_cnt[i] : 0;
    __syncthreads();
    for (int st = SCAN_B / 2; st > 0; st >>= 1) {
        if (threadIdx.x < st) s[threadIdx.x] += s[threadIdx.x + st];
        __syncthreads();
    }
    if (threadIdx.x == 0) g_bsum[blockIdx.x] = s[0];
}

__global__ __launch_bounds__(128)
void scan_bsum_kernel() {
    __shared__ int s[128];
    int t = threadIdx.x;
    int c = (t < NBLK) ? g_bsum[t] : 0;
    s[t] = c;
    __syncthreads();
    for (int st = 1; st < 128; st <<= 1) {
        int v = (t >= st) ? s[t - st] : 0;
        __syncthreads();
        s[t] += v;
        __syncthreads();
    }
    if (t < NBLK) g_bsumex[t] = s[t] - c;   // exclusive
}

__global__ __launch_bounds__(SCAN_B)
void rowptr_kernel() {
    __shared__ int s[SCAN_B];
    int i = blockIdx.x * SCAN_B + threadIdx.x;
    int c = (i < N_NODES) ? g_cnt[i] : 0;
    s[threadIdx.x] = c;
    __syncthreads();
    for (int st = 1; st < SCAN_B; st <<= 1) {
        int v = (threadIdx.x >= st) ? s[threadIdx.x - st] : 0;
        __syncthreads();
        s[threadIdx.x] += v;
        __syncthreads();
    }
    if (i < N_NODES) {
        int excl = g_bsumex[blockIdx.x] + s[threadIdx.x] - c;
        g_rowptr[i] = excl;
        g_cur[i]    = excl;
        if (i == N_NODES - 1) g_rowptr[N_NODES] = excl + c;
    }
}

__global__ __launch_bounds__(256)
void fill_kernel(const int* __restrict__ src, const int* __restrict__ dst,
                 const float* __restrict__ ef) {
    int e = blockIdx.x * 256 + threadIdx.x;
    if (e >= N_EDGES) return;
    int p = atomicAdd(&g_cur[dst[e]], 1);
    g_edge[p] = make_uint2((unsigned)src[e], __float_as_uint(ef[e]));
}

// ---------------------------------------------------------------------------
// Gather-reduce (CSR segment sum, no atomics): red[n] = sum_e w_e * h[src_e]
// One warp per node; lanes 0..24 own one float4 column chunk each.
// ---------------------------------------------------------------------------
__global__ __launch_bounds__(256)
void gather_kernel(const float* __restrict__ h, float* __restrict__ red) {
    const int wid  = threadIdx.x >> 5;
    const int lane = threadIdx.x & 31;
    const int n    = blockIdx.x * 8 + wid;
    if (n >= N_NODES) return;

    const int e0 = g_rowptr[n];
    const int e1 = g_rowptr[n + 1];
    float4 acc = make_float4(0.f, 0.f, 0.f, 0.f);

    int e = e0;
    for (; e + 2 <= e1; e += 2) {
        uint2 p0 = g_edge[e];
        uint2 p1 = g_edge[e + 1];
        float w0 = __uint_as_float(p0.y);
        float w1 = __uint_as_float(p1.y);
        if (lane < 25) {
            float4 v0 = *reinterpret_cast<const float4*>(h + (size_t)p0.x * HID + lane * 4);
            float4 v1 = *reinterpret_cast<const float4*>(h + (size_t)p1.x * HID + lane * 4);
            acc.x += w0 * v0.x + w1 * v1.x;
            acc.y += w0 * v0.y + w1 * v1.y;
            acc.z += w0 * v0.z + w1 * v1.z;
            acc.w += w0 * v0.w + w1 * v1.w;
        }
    }
    if (e < e1) {
        uint2 p0 = g_edge[e];
        float w0 = __uint_as_float(p0.y);
        if (lane < 25) {
            float4 v0 = *reinterpret_cast<const float4*>(h + (size_t)p0.x * HID + lane * 4);
            acc.x += w0 * v0.x; acc.y += w0 * v0.y;
            acc.z += w0 * v0.z; acc.w += w0 * v0.w;
        }
    }
    if (lane < 25)
        *reinterpret_cast<float4*>(red + (size_t)n * HID + lane * 4) = acc;
}

// ---------------------------------------------------------------------------
// Prep: pack B' (= W^T with hi/hi/lo sections) into MMA B-fragment layout.
// ---------------------------------------------------------------------------
__device__ __forceinline__ __nv_bfloat16 wconv(const float* W, int sec, int kk, int col) {
    float w = (kk < 2 * HID && col < HID) ? W[kk * HID + col] : 0.0f;
    __nv_bfloat16 hi = __float2bfloat16(w);
    return (sec == 2) ? __float2bfloat16(w - __bfloat162float(hi)) : hi;
}

__global__ __launch_bounds__(256)
void prep_B_kernel(const float* __restrict__ W1, const float* __restrict__ W2,
                   const float* __restrict__ W3)
{
    int i = blockIdx.x * 256 + threadIdx.x;
    if (i >= 3 * NKF * 2 * 4 * 32) return;
    int l    = i / (NKF * 256);
    int r    = i - l * (NKF * 256);
    int kf   = r >> 8;
    int r2   = r & 255;
    int wn   = r2 >> 7;
    int nbp  = (r2 >> 5) & 3;
    int lane = r2 & 31;

    int sec = kf / 13;
    int kk0 = (kf - sec * 13) * 16 + (lane & 3) * 2;
    int n0  = wn * 64 + (nbp * 2) * 8 + (lane >> 2);
    int n1  = n0 + 8;

    const float* W = (l == 0) ? W1 : (l == 1) ? W2 : W3;

    uint4 o;
    o.x = bf2_u32(__nv_bfloat162(wconv(W, sec, kk0,     n0), wconv(W, sec, kk0 + 1, n0)));
    o.y = bf2_u32(__nv_bfloat162(wconv(W, sec, kk0 + 8, n0), wconv(W, sec, kk0 + 9, n0)));
    o.z = bf2_u32(__nv_bfloat162(wconv(W, sec, kk0,     n1), wconv(W, sec, kk0 + 1, n1)));
    o.w = bf2_u32(__nv_bfloat162(wconv(W, sec, kk0 + 8, n1), wconv(W, sec, kk0 + 9, n1)));
    g_Bfrag[i] = o;
}

// ---------------------------------------------------------------------------
// MPL GEMM (unchanged from round 6)
// ---------------------------------------------------------------------------
__global__ __launch_bounds__(THR, 2)
void mpl_gemm_mma(const float* __restrict__ h,
                  const float* __restrict__ red,
                  const uint4* __restrict__ Bf,
                  const float* __restrict__ b,
                  float* __restrict__ out,
                  int n_nodes)
{
    extern __shared__ __align__(16) uint8_t smem[];
    __nv_bfloat16* sA = reinterpret_cast<__nv_bfloat16*>(smem);
    const uint32_t sbase = smem_u32(smem);

    const int tid    = threadIdx.x;
    const int wid    = tid >> 5;
    const int lane   = tid & 31;
    const int warp_m = wid >> 1;
    const int warp_n = wid & 1;
    const int node0  = blockIdx.x * MT;

    for (int i = tid; i < MT * 52; i += THR) {
        int row = i / 52;
        int kk  = (i - row * 52) * 4;
        int n   = node0 + row;
        float4 v = make_float4(0.f, 0.f, 0.f, 0.f);
        if (n < n_nodes) {
            if (kk < HID)          v = *reinterpret_cast<const float4*>(h + (size_t)n * HID + kk);
            else if (kk < 2 * HID) v = *reinterpret_cast<const float4*>(red + (size_t)n * HID + kk - HID);
        }
        __nv_bfloat162 h0 = __floats2bfloat162_rn(v.x, v.y);
        __nv_bfloat162 h1 = __floats2bfloat162_rn(v.z, v.w);
        __nv_bfloat162 l0 = __floats2bfloat162_rn(v.x - __bfloat162float(h0.x),
                                                  v.y - __bfloat162float(h0.y));
        __nv_bfloat162 l1 = __floats2bfloat162_rn(v.z - __bfloat162float(h1.x),
                                                  v.w - __bfloat162float(h1.y));
        __nv_bfloat16* rp = sA + row * A_STR;
        *reinterpret_cast<uint2*>(rp + kk)       = make_uint2(bf2_u32(h0), bf2_u32(h1));
        *reinterpret_cast<uint2*>(rp + SEC + kk) = make_uint2(bf2_u32(l0), bf2_u32(l1));
    }
    __syncthreads();

    float acc[8][4];
#pragma unroll
    for (int f = 0; f < 8; ++f)
#pragma unroll
        for (int j = 0; j < 4; ++j) acc[f][j] = 0.0f;

    const int lrow  = lane & 15;
    const int lkoff = (lane >> 4) << 3;
    const uint32_t aPtr = sbase + (uint32_t)(((warp_m * 16 + lrow) * A_STR + lkoff) * 2);
    const uint4* bp0 = Bf + (size_t)warp_n * 128 + lane;

#pragma unroll
    for (int sec = 0; sec < 3; ++sec) {
        const uint32_t abase = aPtr + (uint32_t)((sec == 1 ? SEC : 0) * 2);
#pragma unroll
        for (int k13 = 0; k13 < 13; ++k13) {
            uint32_t a0, a1, a2, a3;
            asm volatile("ldmatrix.sync.aligned.m8n8.x4.shared.b16 {%0,%1,%2,%3}, [%4];"
                         : "=r"(a0), "=r"(a1), "=r"(a2), "=r"(a3)
                         : "r"(abase + (uint32_t)(k13 * 32)));
            const uint4* bp = bp0 + (size_t)(sec * 13 + k13) * 256;
#pragma unroll
            for (int nbp = 0; nbp < 4; ++nbp) {
                const uint4 bv = bp[nbp * 32];
                asm volatile("mma.sync.aligned.m16n8k16.row.col.f32.bf16.bf16.f32 "
                             "{%0,%1,%2,%3}, {%4,%5,%6,%7}, {%8,%9}, {%0,%1,%2,%3};"
                             : "+f"(acc[nbp * 2][0]), "+f"(acc[nbp * 2][1]),
                               "+f"(acc[nbp * 2][2]), "+f"(acc[nbp * 2][3])
                             : "r"(a0), "r"(a1), "r"(a2), "r"(a3), "r"(bv.x), "r"(bv.y));
                asm volatile("mma.sync.aligned.m16n8k16.row.col.f32.bf16.bf16.f32 "
                             "{%0,%1,%2,%3}, {%4,%5,%6,%7}, {%8,%9}, {%0,%1,%2,%3};"
                             : "+f"(acc[nbp * 2 + 1][0]), "+f"(acc[nbp * 2 + 1][1]),
                               "+f"(acc[nbp * 2 + 1][2]), "+f"(acc[nbp * 2 + 1][3])
                             : "r"(a0), "r"(a1), "r"(a2), "r"(a3), "r"(bv.z), "r"(bv.w));
            }
        }
    }

    const int gr = lane >> 2;
    const int tc = lane & 3;
    const int r0 = node0 + warp_m * 16 + gr;
    const int r1 = r0 + 8;
#pragma unroll
    for (int f = 0; f < 8; ++f) {
        int col = warp_n * 64 + f * 8 + tc * 2;
        if (col < HID) {
            float b0 = b[col], b1 = b[col + 1];
            if (r0 < n_nodes) {
                float2 v;
                v.x = fmaxf(acc[f][0] + b0, 0.f);
                v.y = fmaxf(acc[f][1] + b1, 0.f);
                *reinterpret_cast<float2*>(out + (size_t)r0 * HID + col) = v;
            }
            if (r1 < n_nodes) {
                float2 v;
                v.x = fmaxf(acc[f][2] + b0, 0.f);
                v.y = fmaxf(acc[f][3] + b1, 0.f);
                *reinterpret_cast<float2*>(out + (size_t)r1 * HID + col) = v;
            }
        }
    }
}

// ---------------------------------------------------------------------------
// Lift GEMM (FFMA; tiny K=16): h = tanh(x @ W_lift + b_lift)
// ---------------------------------------------------------------------------
template <int KDIM>
__global__ __launch_bounds__(512, 1)
void lift_gemm_kernel(const float* __restrict__ in1,
                      const float* __restrict__ W,
                      const float* __restrict__ b,
                      float* __restrict__ out,
                      int n_nodes)
{
    extern __shared__ float sm[];
    constexpr int SSTR = KDIM + 4;
    float* sW  = sm;
    float* sIn = sm + KDIM * 128;

    const int tid   = threadIdx.x;
    const int node0 = blockIdx.x * 128;

    for (int i = tid; i < KDIM * 128; i += 512) {
        int k = i >> 7, c = i & 127;
        sW[i] = (c < HID) ? W[k * HID + c] : 0.0f;
    }
    for (int i = tid; i < 128 * KDIM; i += 512) {
        int nl = i / KDIM, k = i - nl * KDIM;
        int n  = node0 + nl;
        sIn[nl * SSTR + k] = (n < n_nodes) ? in1[n * KDIM + k] : 0.0f;
    }
    __syncthreads();

    const int lane = tid & 31;
    const int wp   = tid >> 5;
    const float* abase = sIn + wp * 8 * SSTR;
    const float* wbase = sW + lane * 4;

    float4 acc[8];
#pragma unroll
    for (int j = 0; j < 8; ++j) acc[j] = make_float4(0.f, 0.f, 0.f, 0.f);

#pragma unroll
    for (int k0 = 0; k0 < KDIM; k0 += 4) {
        const float4 w0 = *reinterpret_cast<const float4*>(wbase + (k0 + 0) * 128);
        const float4 w1 = *reinterpret_cast<const float4*>(wbase + (k0 + 1) * 128);
        const float4 w2 = *reinterpret_cast<const float4*>(wbase + (k0 + 2) * 128);
        const float4 w3 = *reinterpret_cast<const float4*>(wbase + (k0 + 3) * 128);
#pragma unroll
        for (int j = 0; j < 8; ++j) {
            const float4 a = *reinterpret_cast<const float4*>(abase + j * SSTR + k0);
            acc[j].x += a.x * w0.x; acc[j].y += a.x * w0.y; acc[j].z += a.x * w0.z; acc[j].w += a.x * w0.w;
            acc[j].x += a.y * w1.x; acc[j].y += a.y * w1.y; acc[j].z += a.y * w1.z; acc[j].w += a.y * w1.w;
            acc[j].x += a.z * w2.x; acc[j].y += a.z * w2.y; acc[j].z += a.z * w2.z; acc[j].w += a.z * w2.w;
            acc[j].x += a.w * w3.x; acc[j].y += a.w * w3.y; acc[j].z += a.w * w3.z; acc[j].w += a.w * w3.w;
        }
    }

    if (lane < 25) {
        const float4 bias = *reinterpret_cast<const float4*>(b + lane * 4);
#pragma unroll
        for (int j = 0; j < 8; ++j) {
            int n = node0 + wp * 8 + j;
            if (n < n_nodes) {
                float4 r;
                r.x = tanhf(acc[j].x + bias.x); r.y = tanhf(acc[j].y + bias.y);
                r.z = tanhf(acc[j].z + bias.z); r.w = tanhf(acc[j].w + bias.w);
                *reinterpret_cast<float4*>(out + (size_t)n * HID + lane * 4) = r;
            }
        }
    }
}

// ---------------------------------------------------------------------------
// Output head: y[n] = sigmoid(h[n,0:100] @ W_out[100x3] + b_out)
// ---------------------------------------------------------------------------
__global__ __launch_bounds__(256)
void out_kernel(const float* __restrict__ h,
                const float* __restrict__ Wo,
                const float* __restrict__ bo,
                float* __restrict__ y,
                int n_nodes)
{
    __shared__ float sW[HID * OUTF];
    int tid = threadIdx.x;
    for (int i = tid; i < HID * OUTF; i += 256) sW[i] = Wo[i];
    __syncthreads();

    int node = blockIdx.x * 256 + tid;
    if (node >= n_nodes) return;

    float a0 = bo[0], a1 = bo[1], a2 = bo[2];
    const float4* hv = reinterpret_cast<const float4*>(h + (size_t)node * HID);
#pragma unroll
    for (int kb = 0; kb < 25; ++kb) {
        float4 v = hv[kb];
        int k = kb * 4;
        a0 += v.x * sW[(k+0)*3+0]; a1 += v.x * sW[(k+0)*3+1]; a2 += v.x * sW[(k+0)*3+2];
        a0 += v.y * sW[(k+1)*3+0]; a1 += v.y * sW[(k+1)*3+1]; a2 += v.y * sW[(k+1)*3+2];
        a0 += v.z * sW[(k+2)*3+0]; a1 += v.z * sW[(k+2)*3+1]; a2 += v.z * sW[(k+2)*3+2];
        a0 += v.w * sW[(k+3)*3+0]; a1 += v.w * sW[(k+3)*3+1]; a2 += v.w * sW[(k+3)*3+2];
    }
    y[(size_t)node * 3 + 0] = 1.0f / (1.0f + expf(-a0));
    y[(size_t)node * 3 + 1] = 1.0f / (1.0f + expf(-a1));
    y[(size_t)node * 3 + 2] = 1.0f / (1.0f + expf(-a2));
}

// ---------------------------------------------------------------------------
extern "C" void kernel_launch(void* const* d_in, const int* in_sizes, int n_in,
                              void* d_out, int out_size)
{
    const float* x      = (const float*)d_in[0];
    const float* ef     = (const float*)d_in[1];
    const int*   src    = (const int*)  d_in[2];
    const int*   dst    = (const int*)  d_in[3];
    const float* W_lift = (const float*)d_in[4];
    const float* b_lift = (const float*)d_in[5];
    const float* W1     = (const float*)d_in[6];
    const float* b1     = (const float*)d_in[7];
    const float* W2     = (const float*)d_in[8];
    const float* b2     = (const float*)d_in[9];
    const float* W3     = (const float*)d_in[10];
    const float* b3     = (const float*)d_in[11];
    const float* W_out  = (const float*)d_in[12];
    const float* b_out  = (const float*)d_in[13];
    float* y = (float*)d_out;

    float *h, *h2, *red;
    uint4* Bf;
    int* cnt;
    cudaGetSymbolAddress((void**)&h,   g_h);
    cudaGetSymbolAddress((void**)&h2,  g_h2);
    cudaGetSymbolAddress((void**)&red, g_red);
    cudaGetSymbolAddress((void**)&Bf,  g_Bfrag);
    cudaGetSymbolAddress((void**)&cnt, g_cnt);

    const size_t SMEM_LIFT = (IN_F * 128 + 128 * (IN_F + 4)) * sizeof(float);

    cudaFuncSetAttribute((const void*)mpl_gemm_mma,
                         cudaFuncAttributeMaxDynamicSharedMemorySize, SA_BYTES);

    // 0) weight prep + CSR build (once per launch; src/dst invariant across layers)
    prep_B_kernel<<<(3 * NKF * 256 + 255) / 256, 256>>>(W1, W2, W3);
    cudaMemsetAsync(cnt, 0, N_NODES * sizeof(int));
    hist_kernel<<<(N_EDGES + 255) / 256, 256>>>(dst);
    block_sum_kernel<<<NBLK, SCAN_B>>>();
    scan_bsum_kernel<<<1, 128>>>();
    rowptr_kernel<<<NBLK, SCAN_B>>>();
    fill_kernel<<<(N_EDGES + 255) / 256, 256>>>(src, dst, ef);

    // 1) lift
    lift_gemm_kernel<IN_F><<<(N_NODES + 127) / 128, 512, SMEM_LIFT>>>(
        x, W_lift, b_lift, h, N_NODES);

    const int MPL_GRID    = (N_NODES + MT - 1) / MT;   // 1042
    const int GATHER_GRID = (N_NODES + 7) / 8;          // 12500

    const float* bs[3] = { b1, b2, b3 };
    float* bufs[4] = { h, h2, h, h2 };

    for (int l = 0; l < 3; ++l) {
        float* hin  = bufs[l];
        float* hout = bufs[l + 1];
        gather_kernel<<<GATHER_GRID, 256>>>(hin, red);
        mpl_gemm_mma<<<MPL_GRID, THR, SA_BYTES>>>(
            hin, red, Bf + (size_t)l * NKF * 256, bs[l], hout, N_NODES);
    }

    // 3) output head
    out_kernel<<<(N_NODES + 255) / 256, 256>>>(h2, W_out, b_out, y, N_NODES);

    (void)in_sizes; (void)n_in; (void)out_size;
}

// round 8
// speedup vs baseline: 5.6906x; 1.2929x over previous
#include <cuda_runtime.h>
#include <cuda_bf16.h>
#include <math.h>
#include <stdint.h>

#define N_NODES 100000
#define N_EDGES 1600000
#define IN_F    16
#define HID     100
#define OUTF    3

// A' smem: hi section [0,208) + lo section [208,416), row stride 424 bf16
#define SEC    208
#define NKF    39          // B gmem image still has 3 sections of 13 kf
#define MT     80
#define THR    320         // 10 warps: 5 along M x 2 along N
#define A_STR  424
#define SA_BYTES (MT * A_STR * 2)   // 67840

#define SCAN_B 1024
#define NBLK   ((N_NODES + SCAN_B - 1) / SCAN_B)   // 98

// ---------------------------------------------------------------------------
// Scratch (device globals; allocation APIs are forbidden)
// ---------------------------------------------------------------------------
__device__ __align__(16) float g_h  [N_NODES * HID];
__device__ __align__(16) float g_h2 [N_NODES * HID];
__device__ __align__(16) float g_red[N_NODES * HID];
__device__ __align__(16) uint4 g_Bfrag[3 * NKF * 2 * 4 * 32];
// CSR scratch
__device__ int   g_cnt   [N_NODES];
__device__ int   g_rowptr[N_NODES + 1];
__device__ int   g_cur   [N_NODES];
__device__ int   g_bsum  [NBLK];
__device__ int   g_bsumex[NBLK];
__device__ __align__(16) uint2 g_edge[N_EDGES];   // {src, w bits} sorted by dst

__device__ __forceinline__ uint32_t smem_u32(const void* p) {
    uint32_t a;
    asm("{ .reg .u64 t; cvta.to.shared.u64 t, %1; cvt.u32.u64 %0, t; }" : "=r"(a) : "l"(p));
    return a;
}
__device__ __forceinline__ uint32_t bf2_u32(__nv_bfloat162 v) {
    return *reinterpret_cast<uint32_t*>(&v);
}

#define LDSM4(r, addr)                                                           \
    asm volatile("ldmatrix.sync.aligned.m8n8.x4.shared.b16 {%0,%1,%2,%3}, [%4];" \
                 : "=r"((r)[0]), "=r"((r)[1]), "=r"((r)[2]), "=r"((r)[3])        \
                 : "r"(addr))

#define MMA16816(acc, a, bx, by)                                                 \
    asm volatile("mma.sync.aligned.m16n8k16.row.col.f32.bf16.bf16.f32 "          \
                 "{%0,%1,%2,%3}, {%4,%5,%6,%7}, {%8,%9}, {%0,%1,%2,%3};"         \
                 : "+f"((acc)[0]), "+f"((acc)[1]), "+f"((acc)[2]), "+f"((acc)[3])\
                 : "r"((a)[0]), "r"((a)[1]), "r"((a)[2]), "r"((a)[3]),           \
                   "r"(bx), "r"(by))

// ---------------------------------------------------------------------------
// CSR build
// ---------------------------------------------------------------------------
__global__ __launch_bounds__(256)
void hist_kernel(const int* __restrict__ dst) {
    int e = blockIdx.x * 256 + threadIdx.x;
    if (e < N_EDGES) atomicAdd(&g_cnt[dst[e]], 1);
}

__global__ __launch_bounds__(SCAN_B)
void block_sum_kernel() {
    __shared__ int s[SCAN_B];
    int i = blockIdx.x * SCAN_B + threadIdx.x;
    s[threadIdx.x] = (i < N_NODES) ? g_cnt[i] : 0;
    __syncthreads();
    for (int st = SCAN_B / 2; st > 0; st >>= 1) {
        if (threadIdx.x < st) s[threadIdx.x] += s[threadIdx.x + st];
        __syncthreads();
    }
    if (threadIdx.x == 0) g_bsum[blockIdx.x] = s[0];
}

__global__ __launch_bounds__(128)
void scan_bsum_kernel() {
    __shared__ int s[128];
    int t = threadIdx.x;
    int c = (t < NBLK) ? g_bsum[t] : 0;
    s[t] = c;
    __syncthreads();
    for (int st = 1; st < 128; st <<= 1) {
        int v = (t >= st) ? s[t - st] : 0;
        __syncthreads();
        s[t] += v;
        __syncthreads();
    }
    if (t < NBLK) g_bsumex[t] = s[t] - c;   // exclusive
}

__global__ __launch_bounds__(SCAN_B)
void rowptr_kernel() {
    __shared__ int s[SCAN_B];
    int i = blockIdx.x * SCAN_B + threadIdx.x;
    int c = (i < N_NODES) ? g_cnt[i] : 0;
    s[threadIdx.x] = c;
    __syncthreads();
    for (int st = 1; st < SCAN_B; st <<= 1) {
        int v = (threadIdx.x >= st) ? s[threadIdx.x - st] : 0;
        __syncthreads();
        s[threadIdx.x] += v;
        __syncthreads();
    }
    if (i < N_NODES) {
        int excl = g_bsumex[blockIdx.x] + s[threadIdx.x] - c;
        g_rowptr[i] = excl;
        g_cur[i]    = excl;
        if (i == N_NODES - 1) g_rowptr[N_NODES] = excl + c;
    }
}

__global__ __launch_bounds__(256)
void fill_kernel(const int* __restrict__ src, const int* __restrict__ dst,
                 const float* __restrict__ ef) {
    int e = blockIdx.x * 256 + threadIdx.x;
    if (e >= N_EDGES) return;
    int p = atomicAdd(&g_cur[dst[e]], 1);
    g_edge[p] = make_uint2((unsigned)src[e], __float_as_uint(ef[e]));
}

// ---------------------------------------------------------------------------
// Gather-reduce (CSR segment sum): red[n] = sum_e w_e * h[src_e]
// ---------------------------------------------------------------------------
__global__ __launch_bounds__(256)
void gather_kernel(const float* __restrict__ h, float* __restrict__ red) {
    const int wid  = threadIdx.x >> 5;
    const int lane = threadIdx.x & 31;
    const int n    = blockIdx.x * 8 + wid;
    if (n >= N_NODES) return;

    const int e0 = g_rowptr[n];
    const int e1 = g_rowptr[n + 1];
    float4 acc = make_float4(0.f, 0.f, 0.f, 0.f);

    int e = e0;
    for (; e + 2 <= e1; e += 2) {
        uint2 p0 = g_edge[e];
        uint2 p1 = g_edge[e + 1];
        float w0 = __uint_as_float(p0.y);
        float w1 = __uint_as_float(p1.y);
        if (lane < 25) {
            float4 v0 = *reinterpret_cast<const float4*>(h + (size_t)p0.x * HID + lane * 4);
            float4 v1 = *reinterpret_cast<const float4*>(h + (size_t)p1.x * HID + lane * 4);
            acc.x += w0 * v0.x + w1 * v1.x;
            acc.y += w0 * v0.y + w1 * v1.y;
            acc.z += w0 * v0.z + w1 * v1.z;
            acc.w += w0 * v0.w + w1 * v1.w;
        }
    }
    if (e < e1) {
        uint2 p0 = g_edge[e];
        float w0 = __uint_as_float(p0.y);
        if (lane < 25) {
            float4 v0 = *reinterpret_cast<const float4*>(h + (size_t)p0.x * HID + lane * 4);
            acc.x += w0 * v0.x; acc.y += w0 * v0.y;
            acc.z += w0 * v0.z; acc.w += w0 * v0.w;
        }
    }
    if (lane < 25)
        *reinterpret_cast<float4*>(red + (size_t)n * HID + lane * 4) = acc;
}

// ---------------------------------------------------------------------------
// Prep: pack B' (= W^T with hi/hi/lo sections) into MMA B-fragment layout.
// ---------------------------------------------------------------------------
__device__ __forceinline__ __nv_bfloat16 wconv(const float* W, int sec, int kk, int col) {
    float w = (kk < 2 * HID && col < HID) ? W[kk * HID + col] : 0.0f;
    __nv_bfloat16 hi = __float2bfloat16(w);
    return (sec == 2) ? __float2bfloat16(w - __bfloat162float(hi)) : hi;
}

__global__ __launch_bounds__(256)
void prep_B_kernel(const float* __restrict__ W1, const float* __restrict__ W2,
                   const float* __restrict__ W3)
{
    int i = blockIdx.x * 256 + threadIdx.x;
    if (i >= 3 * NKF * 2 * 4 * 32) return;
    int l    = i / (NKF * 256);
    int r    = i - l * (NKF * 256);
    int kf   = r >> 8;
    int r2   = r & 255;
    int wn   = r2 >> 7;
    int nbp  = (r2 >> 5) & 3;
    int lane = r2 & 31;

    int sec = kf / 13;
    int kk0 = (kf - sec * 13) * 16 + (lane & 3) * 2;
    int n0  = wn * 64 + (nbp * 2) * 8 + (lane >> 2);
    int n1  = n0 + 8;

    const float* W = (l == 0) ? W1 : (l == 1) ? W2 : W3;

    uint4 o;
    o.x = bf2_u32(__nv_bfloat162(wconv(W, sec, kk0,     n0), wconv(W, sec, kk0 + 1, n0)));
    o.y = bf2_u32(__nv_bfloat162(wconv(W, sec, kk0 + 8, n0), wconv(W, sec, kk0 + 9, n0)));
    o.z = bf2_u32(__nv_bfloat162(wconv(W, sec, kk0,     n1), wconv(W, sec, kk0 + 1, n1)));
    o.w = bf2_u32(__nv_bfloat162(wconv(W, sec, kk0 + 8, n1), wconv(W, sec, kk0 + 9, n1)));
    g_Bfrag[i] = o;
}

// ---------------------------------------------------------------------------
// MPL GEMM: out[n,0:100] = relu( concat(h[n], red[n]) @ W + b )
// Phase 1: B_hi loaded once per kf, fires A_hi*B_hi AND A_lo*B_hi (16 MMA/kf).
// Phase 2: A_hi*B_lo (8 MMA/kf). B register-prefetched at distance 2,
// A ldmatrix-prefetched at distance 1. No mainloop syncs.
// ---------------------------------------------------------------------------
__global__ __launch_bounds__(THR, 2)
void mpl_gemm_mma(const float* __restrict__ h,
                  const float* __restrict__ red,
                  const uint4* __restrict__ Bf,
                  const float* __restrict__ b,
                  float* __restrict__ out,
                  int n_nodes)
{
    extern __shared__ __align__(16) uint8_t smem[];
    __nv_bfloat16* sA = reinterpret_cast<__nv_bfloat16*>(smem);
    const uint32_t sbase = smem_u32(smem);

    const int tid    = threadIdx.x;
    const int wid    = tid >> 5;
    const int lane   = tid & 31;
    const int warp_m = wid >> 1;         // 0..4
    const int warp_n = wid & 1;          // 0..1
    const int node0  = blockIdx.x * MT;

    // ---- fill A' once: hi at [0,208), lo at [208,416) ----
    for (int i = tid; i < MT * 52; i += THR) {
        int row = i / 52;
        int kk  = (i - row * 52) * 4;
        int n   = node0 + row;
        float4 v = make_float4(0.f, 0.f, 0.f, 0.f);
        if (n < n_nodes) {
            if (kk < HID)          v = *reinterpret_cast<const float4*>(h + (size_t)n * HID + kk);
            else if (kk < 2 * HID) v = *reinterpret_cast<const float4*>(red + (size_t)n * HID + kk - HID);
        }
        __nv_bfloat162 h0 = __floats2bfloat162_rn(v.x, v.y);
        __nv_bfloat162 h1 = __floats2bfloat162_rn(v.z, v.w);
        __nv_bfloat162 l0 = __floats2bfloat162_rn(v.x - __bfloat162float(h0.x),
                                                  v.y - __bfloat162float(h0.y));
        __nv_bfloat162 l1 = __floats2bfloat162_rn(v.z - __bfloat162float(h1.x),
                                                  v.w - __bfloat162float(h1.y));
        __nv_bfloat16* rp = sA + row * A_STR;
        *reinterpret_cast<uint2*>(rp + kk)       = make_uint2(bf2_u32(h0), bf2_u32(h1));
        *reinterpret_cast<uint2*>(rp + SEC + kk) = make_uint2(bf2_u32(l0), bf2_u32(l1));
    }
    __syncthreads();

    float acc[8][4];
#pragma unroll
    for (int f = 0; f < 8; ++f)
#pragma unroll
        for (int j = 0; j < 4; ++j) acc[f][j] = 0.0f;

    const int lrow  = lane & 15;
    const int lkoff = (lane >> 4) << 3;
    const uint32_t aHi = sbase + (uint32_t)(((warp_m * 16 + lrow) * A_STR + lkoff) * 2);
    const uint32_t aLo = aHi + SEC * 2;
    const uint4* bHi = Bf + (size_t)warp_n * 128 + lane;                // kf 0..12
    const uint4* bLo = Bf + (size_t)26 * 256 + (size_t)warp_n * 128 + lane;

    uint32_t ah[2][4], al[2][4];
    uint4 bb[2][4];

    // ================= Phase 1: B_hi x (A_hi + A_lo) =================
    LDSM4(ah[0], aHi);
    LDSM4(al[0], aLo);
#pragma unroll
    for (int nbp = 0; nbp < 4; ++nbp) {
        bb[0][nbp] = bHi[nbp * 32];
        bb[1][nbp] = bHi[256 + nbp * 32];
    }
#pragma unroll
    for (int k = 0; k < 13; ++k) {
        const int cur = k & 1, nxt = cur ^ 1;
        if (k + 1 < 13) {
            LDSM4(ah[nxt], aHi + (uint32_t)((k + 1) * 32));
            LDSM4(al[nxt], aLo + (uint32_t)((k + 1) * 32));
        }
#pragma unroll
        for (int nbp = 0; nbp < 4; ++nbp) {
            const uint4 bv = bb[cur][nbp];
            MMA16816(acc[nbp * 2],     ah[cur], bv.x, bv.y);
            MMA16816(acc[nbp * 2 + 1], ah[cur], bv.z, bv.w);
            MMA16816(acc[nbp * 2],     al[cur], bv.x, bv.y);
            MMA16816(acc[nbp * 2 + 1], al[cur], bv.z, bv.w);
            if (k + 2 < 13) bb[cur][nbp] = bHi[(k + 2) * 256 + nbp * 32];
        }
    }

    // ================= Phase 2: B_lo x A_hi =================
    LDSM4(ah[0], aHi);
#pragma unroll
    for (int nbp = 0; nbp < 4; ++nbp) {
        bb[0][nbp] = bLo[nbp * 32];
        bb[1][nbp] = bLo[256 + nbp * 32];
    }
#pragma unroll
    for (int k = 0; k < 13; ++k) {
        const int cur = k & 1, nxt = cur ^ 1;
        if (k + 1 < 13) LDSM4(ah[nxt], aHi + (uint32_t)((k + 1) * 32));
#pragma unroll
        for (int nbp = 0; nbp < 4; ++nbp) {
            const uint4 bv = bb[cur][nbp];
            MMA16816(acc[nbp * 2],     ah[cur], bv.x, bv.y);
            MMA16816(acc[nbp * 2 + 1], ah[cur], bv.z, bv.w);
            if (k + 2 < 13) bb[cur][nbp] = bLo[(k + 2) * 256 + nbp * 32];
        }
    }

    // ---- epilogue: bias + relu + float2 stores ----
    const int gr = lane >> 2;
    const int tc = lane & 3;
    const int r0 = node0 + warp_m * 16 + gr;
    const int r1 = r0 + 8;
#pragma unroll
    for (int f = 0; f < 8; ++f) {
        int col = warp_n * 64 + f * 8 + tc * 2;
        if (col < HID) {
            float b0 = b[col], b1 = b[col + 1];
            if (r0 < n_nodes) {
                float2 v;
                v.x = fmaxf(acc[f][0] + b0, 0.f);
                v.y = fmaxf(acc[f][1] + b1, 0.f);
                *reinterpret_cast<float2*>(out + (size_t)r0 * HID + col) = v;
            }
            if (r1 < n_nodes) {
                float2 v;
                v.x = fmaxf(acc[f][2] + b0, 0.f);
                v.y = fmaxf(acc[f][3] + b1, 0.f);
                *reinterpret_cast<float2*>(out + (size_t)r1 * HID + col) = v;
            }
        }
    }
}

// ---------------------------------------------------------------------------
// Lift GEMM (FFMA; tiny K=16): h = tanh(x @ W_lift + b_lift)
// ---------------------------------------------------------------------------
template <int KDIM>
__global__ __launch_bounds__(512, 1)
void lift_gemm_kernel(const float* __restrict__ in1,
                      const float* __restrict__ W,
                      const float* __restrict__ b,
                      float* __restrict__ out,
                      int n_nodes)
{
    extern __shared__ float sm[];
    constexpr int SSTR = KDIM + 4;
    float* sW  = sm;
    float* sIn = sm + KDIM * 128;

    const int tid   = threadIdx.x;
    const int node0 = blockIdx.x * 128;

    for (int i = tid; i < KDIM * 128; i += 512) {
        int k = i >> 7, c = i & 127;
        sW[i] = (c < HID) ? W[k * HID + c] : 0.0f;
    }
    for (int i = tid; i < 128 * KDIM; i += 512) {
        int nl = i / KDIM, k = i - nl * KDIM;
        int n  = node0 + nl;
        sIn[nl * SSTR + k] = (n < n_nodes) ? in1[n * KDIM + k] : 0.0f;
    }
    __syncthreads();

    const int lane = tid & 31;
    const int wp   = tid >> 5;
    const float* abase = sIn + wp * 8 * SSTR;
    const float* wbase = sW + lane * 4;

    float4 acc[8];
#pragma unroll
    for (int j = 0; j < 8; ++j) acc[j] = make_float4(0.f, 0.f, 0.f, 0.f);

#pragma unroll
    for (int k0 = 0; k0 < KDIM; k0 += 4) {
        const float4 w0 = *reinterpret_cast<const float4*>(wbase + (k0 + 0) * 128);
        const float4 w1 = *reinterpret_cast<const float4*>(wbase + (k0 + 1) * 128);
        const float4 w2 = *reinterpret_cast<const float4*>(wbase + (k0 + 2) * 128);
        const float4 w3 = *reinterpret_cast<const float4*>(wbase + (k0 + 3) * 128);
#pragma unroll
        for (int j = 0; j < 8; ++j) {
            const float4 a = *reinterpret_cast<const float4*>(abase + j * SSTR + k0);
            acc[j].x += a.x * w0.x; acc[j].y += a.x * w0.y; acc[j].z += a.x * w0.z; acc[j].w += a.x * w0.w;
            acc[j].x += a.y * w1.x; acc[j].y += a.y * w1.y; acc[j].z += a.y * w1.z; acc[j].w += a.y * w1.w;
            acc[j].x += a.z * w2.x; acc[j].y += a.z * w2.y; acc[j].z += a.z * w2.z; acc[j].w += a.z * w2.w;
            acc[j].x += a.w * w3.x; acc[j].y += a.w * w3.y; acc[j].z += a.w * w3.z; acc[j].w += a.w * w3.w;
        }
    }

    if (lane < 25) {
        const float4 bias = *reinterpret_cast<const float4*>(b + lane * 4);
#pragma unroll
        for (int j = 0; j < 8; ++j) {
            int n = node0 + wp * 8 + j;
            if (n < n_nodes) {
                float4 r;
                r.x = tanhf(acc[j].x + bias.x); r.y = tanhf(acc[j].y + bias.y);
                r.z = tanhf(acc[j].z + bias.z); r.w = tanhf(acc[j].w + bias.w);
                *reinterpret_cast<float4*>(out + (size_t)n * HID + lane * 4) = r;
            }
        }
    }
}

// ---------------------------------------------------------------------------
// Output head: y[n] = sigmoid(h[n,0:100] @ W_out[100x3] + b_out)
// ---------------------------------------------------------------------------
__global__ __launch_bounds__(256)
void out_kernel(const float* __restrict__ h,
                const float* __restrict__ Wo,
                const float* __restrict__ bo,
                float* __restrict__ y,
                int n_nodes)
{
    __shared__ float sW[HID * OUTF];
    int tid = threadIdx.x;
    for (int i = tid; i < HID * OUTF; i += 256) sW[i] = Wo[i];
    __syncthreads();

    int node = blockIdx.x * 256 + tid;
    if (node >= n_nodes) return;

    float a0 = bo[0], a1 = bo[1], a2 = bo[2];
    const float4* hv = reinterpret_cast<const float4*>(h + (size_t)node * HID);
#pragma unroll
    for (int kb = 0; kb < 25; ++kb) {
        float4 v = hv[kb];
        int k = kb * 4;
        a0 += v.x * sW[(k+0)*3+0]; a1 += v.x * sW[(k+0)*3+1]; a2 += v.x * sW[(k+0)*3+2];
        a0 += v.y * sW[(k+1)*3+0]; a1 += v.y * sW[(k+1)*3+1]; a2 += v.y * sW[(k+1)*3+2];
        a0 += v.z * sW[(k+2)*3+0]; a1 += v.z * sW[(k+2)*3+1]; a2 += v.z * sW[(k+2)*3+2];
        a0 += v.w * sW[(k+3)*3+0]; a1 += v.w * sW[(k+3)*3+1]; a2 += v.w * sW[(k+3)*3+2];
    }
    y[(size_t)node * 3 + 0] = 1.0f / (1.0f + expf(-a0));
    y[(size_t)node * 3 + 1] = 1.0f / (1.0f + expf(-a1));
    y[(size_t)node * 3 + 2] = 1.0f / (1.0f + expf(-a2));
}

// ---------------------------------------------------------------------------
extern "C" void kernel_launch(void* const* d_in, const int* in_sizes, int n_in,
                              void* d_out, int out_size)
{
    const float* x      = (const float*)d_in[0];
    const float* ef     = (const float*)d_in[1];
    const int*   src    = (const int*)  d_in[2];
    const int*   dst    = (const int*)  d_in[3];
    const float* W_lift = (const float*)d_in[4];
    const float* b_lift = (const float*)d_in[5];
    const float* W1     = (const float*)d_in[6];
    const float* b1     = (const float*)d_in[7];
    const float* W2     = (const float*)d_in[8];
    const float* b2     = (const float*)d_in[9];
    const float* W3     = (const float*)d_in[10];
    const float* b3     = (const float*)d_in[11];
    const float* W_out  = (const float*)d_in[12];
    const float* b_out  = (const float*)d_in[13];
    float* y = (float*)d_out;

    float *h, *h2, *red;
    uint4* Bf;
    int* cnt;
    cudaGetSymbolAddress((void**)&h,   g_h);
    cudaGetSymbolAddress((void**)&h2,  g_h2);
    cudaGetSymbolAddress((void**)&red, g_red);
    cudaGetSymbolAddress((void**)&Bf,  g_Bfrag);
    cudaGetSymbolAddress((void**)&cnt, g_cnt);

    const size_t SMEM_LIFT = (IN_F * 128 + 128 * (IN_F + 4)) * sizeof(float);

    cudaFuncSetAttribute((const void*)mpl_gemm_mma,
                         cudaFuncAttributeMaxDynamicSharedMemorySize, SA_BYTES);

    // 0) weight prep + CSR build (once per launch)
    prep_B_kernel<<<(3 * NKF * 256 + 255) / 256, 256>>>(W1, W2, W3);
    cudaMemsetAsync(cnt, 0, N_NODES * sizeof(int));
    hist_kernel<<<(N_EDGES + 255) / 256, 256>>>(dst);
    block_sum_kernel<<<NBLK, SCAN_B>>>();
    scan_bsum_kernel<<<1, 128>>>();
    rowptr_kernel<<<NBLK, SCAN_B>>>();
    fill_kernel<<<(N_EDGES + 255) / 256, 256>>>(src, dst, ef);

    // 1) lift
    lift_gemm_kernel<IN_F><<<(N_NODES + 127) / 128, 512, SMEM_LIFT>>>(
        x, W_lift, b_lift, h, N_NODES);

    const int MPL_GRID    = (N_NODES + MT - 1) / MT;   // 1250
    const int GATHER_GRID = (N_NODES + 7) / 8;          // 12500

    const float* bs[3] = { b1, b2, b3 };
    float* bufs[4] = { h, h2, h, h2 };

    for (int l = 0; l < 3; ++l) {
        float* hin  = bufs[l];
        float* hout = bufs[l + 1];
        gather_kernel<<<GATHER_GRID, 256>>>(hin, red);
        mpl_gemm_mma<<<MPL_GRID, THR, SA_BYTES>>>(
            hin, red, Bf + (size_t)l * NKF * 256, bs[l], hout, N_NODES);
    }

    // 3) output head
    out_kernel<<<(N_NODES + 255) / 256, 256>>>(h2, W_out, b_out, y, N_NODES);

    (void)in_sizes; (void)n_in; (void)out_size;
}